// round 4
// baseline (speedup 1.0000x reference)
#include <cuda_runtime.h>
#include <cstdint>
#include <cstddef>

// Problem constants
#define NB    8
#define NCH   256
#define NTOK  4096                 // H*W
#define CHB   ((size_t)NCH * NTOK)
#define NNB   ((size_t)NTOK * NTOK)

// Static scratch
__device__ float g_hn[NB * CHB];   // groupnorm output
__device__ float g_q [NB * CHB];   // q [ch][tok], later reused for ao [ch][tok]
__device__ float g_k [NB * CHB];   // k [ch][tok]
__device__ float g_v [NB * CHB];   // v [ch][tok]
__device__ float g_qT[NB * CHB];   // qT [tok][ch] (tf32-rounded)
__device__ float g_kT[NB * CHB];   // kT [tok][ch] (tf32-rounded)
__device__ float g_s [NB * NNB];   // logits / probs
__device__ int   g_fragmode;       // mma fragment-order mode from self-test

__device__ __forceinline__ float tf32r(float x) {
    unsigned u;
    asm("cvt.rna.tf32.f32 %0, %1;" : "=r"(u) : "f"(x));
    return __uint_as_float(u);
}

__device__ __forceinline__ void mma8(float* c, unsigned a0, unsigned a1,
                                     unsigned a2, unsigned a3,
                                     unsigned b0, unsigned b1)
{
    asm volatile(
        "mma.sync.aligned.m16n8k8.row.col.f32.tf32.tf32.f32 "
        "{%0,%1,%2,%3},{%4,%5,%6,%7},{%8,%9},{%0,%1,%2,%3};"
        : "+f"(c[0]), "+f"(c[1]), "+f"(c[2]), "+f"(c[3])
        : "r"(a0), "r"(a1), "r"(a2), "r"(a3), "r"(b0), "r"(b1));
}

// ---------------------------------------------------------------------------
// Self-test: determine the fragment register ordering the HW actually uses.
// ---------------------------------------------------------------------------
__global__ void mma_selftest()
{
    __shared__ float A[16][8], B[8][8], D[16][8];
    int t = threadIdx.x;
    if (t == 0) {
        for (int r = 0; r < 16; r++)
            for (int c = 0; c < 8; c++)
                A[r][c] = (float)((r * c + 3 * r + 5 * c + 1) % 9 - 4) * 0.25f;
        for (int n = 0; n < 8; n++)
            for (int k = 0; k < 8; k++)
                B[n][k] = (float)((n * k + 2 * n + 7 * k + 3) % 9 - 4) * 0.25f;
        for (int m = 0; m < 16; m++)
            for (int n = 0; n < 8; n++) {
                float s = 0.f;
                for (int k = 0; k < 8; k++) s += A[m][k] * B[n][k];
                D[m][n] = s;
            }
    }
    __syncwarp();
    int lr = t >> 2, lc = t & 3;
    unsigned p0 = __float_as_uint(A[lr][lc]);
    unsigned p1 = __float_as_uint(A[lr + 8][lc]);
    unsigned p2 = __float_as_uint(A[lr][lc + 4]);
    unsigned p3 = __float_as_uint(A[lr + 8][lc + 4]);
    unsigned q0 = __float_as_uint(B[lr][lc]);
    unsigned q1 = __float_as_uint(B[lr][lc + 4]);
    int best = 0;
    bool found = false;
    for (int mode = 0; mode < 4; mode++) {
        float c[4] = {0.f, 0.f, 0.f, 0.f};
        unsigned a1 = (mode & 1) ? p2 : p1;
        unsigned a2 = (mode & 1) ? p1 : p2;
        unsigned b0 = (mode & 2) ? q1 : q0;
        unsigned b1 = (mode & 2) ? q0 : q1;
        mma8(c, p0, a1, a2, p3, b0, b1);
        bool ok = fabsf(c[0] - D[lr][2 * lc])         < 1e-3f &&
                  fabsf(c[1] - D[lr][2 * lc + 1])     < 1e-3f &&
                  fabsf(c[2] - D[lr + 8][2 * lc])     < 1e-3f &&
                  fabsf(c[3] - D[lr + 8][2 * lc + 1]) < 1e-3f;
        bool allok = __all_sync(0xffffffffu, ok);
        if (allok && !found) { best = mode; found = true; }
    }
    if (t == 0) g_fragmode = best;
}

// ---------------------------------------------------------------------------
// GroupNorm (round-1 proven version, verbatim).
// ---------------------------------------------------------------------------
__global__ __launch_bounds__(256) void groupnorm_kernel(
    const float* __restrict__ x, const float* __restrict__ sc,
    const float* __restrict__ bi, float* __restrict__ out)
{
    int b = blockIdx.x >> 5;
    int g = blockIdx.x & 31;
    size_t base = ((size_t)b * NCH + (size_t)g * 8) * NTOK;
    const float4* px = (const float4*)(x + base);
    float4* po = (float4*)(out + base);
    int t = threadIdx.x;

    float s = 0.f, ss = 0.f;
#pragma unroll
    for (int r = 0; r < 32; r++) {
        float4 f = px[r * 256 + t];
        s  += f.x + f.y + f.z + f.w;
        ss += f.x * f.x + f.y * f.y + f.z * f.z + f.w * f.w;
    }
#pragma unroll
    for (int o = 16; o; o >>= 1) {
        s  += __shfl_xor_sync(0xffffffffu, s, o);
        ss += __shfl_xor_sync(0xffffffffu, ss, o);
    }
    __shared__ float rs[8], rss[8];
    __shared__ float s_mean, s_rstd;
    if ((t & 31) == 0) { rs[t >> 5] = s; rss[t >> 5] = ss; }
    __syncthreads();
    if (t == 0) {
        float S = 0.f, SS = 0.f;
#pragma unroll
        for (int i = 0; i < 8; i++) { S += rs[i]; SS += rss[i]; }
        float m = S * (1.f / 32768.f);
        float var = SS * (1.f / 32768.f) - m * m;
        s_mean = m;
        s_rstd = rsqrtf(var + 1e-6f);
    }
    __syncthreads();
    float m = s_mean, rstd = s_rstd;
#pragma unroll
    for (int r = 0; r < 32; r++) {
        int idx = r * 256 + t;
        int c = g * 8 + (idx >> 10);
        float a = sc[c] * rstd;
        float bb = bi[c] - m * a;
        float4 f = px[idx];
        po[idx] = make_float4(f.x * a + bb, f.y * a + bb, f.z * a + bb, f.w * a + bb);
    }
}

// ---------------------------------------------------------------------------
// Round-1 proven SIMT GEMM (verbatim). Used for projections + final.
// ---------------------------------------------------------------------------
#define BM 128
#define BN 128
#define BK 8
#define ASTR 132

template<int A_KMAJOR, int B_TRANS, int HAS_BIAS, int RESID>
__global__ __launch_bounds__(256) void gemm128(
    const float* __restrict__ A, const float* __restrict__ B,
    float* __restrict__ C, const float* __restrict__ bias,
    const float* __restrict__ resid,
    int M, int N, int K, float alpha, float outscale,
    size_t batchA, size_t batchB, size_t batchC)
{
    __shared__ float as[BK * ASTR];
    __shared__ float bs[BK * ASTR];

    int t  = threadIdx.x;
    int tx = t & 15, ty = t >> 4;
    int m0 = blockIdx.y * BM, n0 = blockIdx.x * BN;
    size_t z = blockIdx.z;
    A += z * batchA;
    B += z * batchB;

    int ldA = A_KMAJOR ? M : K;
    int ldB = B_TRANS ? K : N;

    float acc[8][8];
#pragma unroll
    for (int i = 0; i < 8; i++)
#pragma unroll
        for (int j = 0; j < 8; j++) acc[i][j] = 0.f;

    const int nch = K / BK;
    float4 aReg, bReg;

    if (A_KMAJOR) {
        aReg = *(const float4*)&A[(size_t)((t >> 5)) * ldA + m0 + (t & 31) * 4];
    } else {
        aReg = *(const float4*)&A[(size_t)(m0 + (t >> 1)) * ldA + (t & 1) * 4];
    }
    if (!B_TRANS) {
        bReg = *(const float4*)&B[(size_t)((t >> 5)) * ldB + n0 + (t & 31) * 4];
    } else {
        bReg = *(const float4*)&B[(size_t)(n0 + (t >> 1)) * ldB + (t & 1) * 4];
    }

    for (int kt = 0; kt < nch; kt++) {
        if (A_KMAJOR) {
            *(float4*)&as[(t >> 5) * ASTR + (t & 31) * 4] = aReg;
        } else {
            int i = t >> 1, kb = (t & 1) * 4;
            as[(kb + 0) * ASTR + i] = aReg.x;
            as[(kb + 1) * ASTR + i] = aReg.y;
            as[(kb + 2) * ASTR + i] = aReg.z;
            as[(kb + 3) * ASTR + i] = aReg.w;
        }
        if (!B_TRANS) {
            *(float4*)&bs[(t >> 5) * ASTR + (t & 31) * 4] = bReg;
        } else {
            int j = t >> 1, kb = (t & 1) * 4;
            bs[(kb + 0) * ASTR + j] = bReg.x;
            bs[(kb + 1) * ASTR + j] = bReg.y;
            bs[(kb + 2) * ASTR + j] = bReg.z;
            bs[(kb + 3) * ASTR + j] = bReg.w;
        }
        __syncthreads();

        if (kt + 1 < nch) {
            int kofs = (kt + 1) * BK;
            if (A_KMAJOR) {
                aReg = *(const float4*)&A[(size_t)(kofs + (t >> 5)) * ldA + m0 + (t & 31) * 4];
            } else {
                aReg = *(const float4*)&A[(size_t)(m0 + (t >> 1)) * ldA + kofs + (t & 1) * 4];
            }
            if (!B_TRANS) {
                bReg = *(const float4*)&B[(size_t)(kofs + (t >> 5)) * ldB + n0 + (t & 31) * 4];
            } else {
                bReg = *(const float4*)&B[(size_t)(n0 + (t >> 1)) * ldB + kofs + (t & 1) * 4];
            }
        }

#pragma unroll
        for (int kk = 0; kk < BK; kk++) {
            float a[8], b[8];
            *(float4*)&a[0] = *(const float4*)&as[kk * ASTR + ty * 8];
            *(float4*)&a[4] = *(const float4*)&as[kk * ASTR + ty * 8 + 4];
            *(float4*)&b[0] = *(const float4*)&bs[kk * ASTR + tx * 8];
            *(float4*)&b[4] = *(const float4*)&bs[kk * ASTR + tx * 8 + 4];
#pragma unroll
            for (int i = 0; i < 8; i++)
#pragma unroll
                for (int j = 0; j < 8; j++) acc[i][j] = fmaf(a[i], b[j], acc[i][j]);
        }
        __syncthreads();
    }

    int mb = m0 + ty * 8, nb = n0 + tx * 8;
#pragma unroll
    for (int i = 0; i < 8; i++) {
        int m = mb + i;
        float bv = HAS_BIAS ? bias[m] : 0.f;
        size_t cbase = z * batchC + (size_t)m * N + nb;
#pragma unroll
        for (int jj = 0; jj < 2; jj++) {
            float4 o;
            o.x = acc[i][jj * 4 + 0] * alpha + bv;
            o.y = acc[i][jj * 4 + 1] * alpha + bv;
            o.z = acc[i][jj * 4 + 2] * alpha + bv;
            o.w = acc[i][jj * 4 + 3] * alpha + bv;
            if (RESID) {
                float4 rv = *(const float4*)&resid[cbase + jj * 4];
                o.x = (o.x + rv.x) * outscale;
                o.y = (o.y + rv.y) * outscale;
                o.z = (o.z + rv.z) * outscale;
                o.w = (o.w + rv.w) * outscale;
            } else if (outscale != 1.f) {
                o.x *= outscale; o.y *= outscale; o.z *= outscale; o.w *= outscale;
            }
            *(float4*)&C[cbase + jj * 4] = o;
        }
    }
}

// ---------------------------------------------------------------------------
// Transpose [256][4096] -> [4096][256] per batch, tf32-rounded output.
// ---------------------------------------------------------------------------
__global__ __launch_bounds__(256) void transpose_kernel(
    const float* __restrict__ in, float* __restrict__ out)
{
    __shared__ float tile[32][33];
    size_t z = blockIdx.z;
    const float* ip = in + z * CHB;
    float* op = out + z * CHB;
    int n0 = blockIdx.x * 32, c0 = blockIdx.y * 32;
    int tx = threadIdx.x & 31, ty = threadIdx.x >> 5;  // ty 0..7
#pragma unroll
    for (int j = 0; j < 32; j += 8)
        tile[ty + j][tx] = ip[(size_t)(c0 + ty + j) * NTOK + n0 + tx];
    __syncthreads();
#pragma unroll
    for (int j = 0; j < 32; j += 8)
        op[(size_t)(n0 + ty + j) * NCH + c0 + tx] = tf32r(tile[tx][ty + j]);
}

// ---------------------------------------------------------------------------
// MMA tile core + gemm_big (verbatim from round 3 — the code under test).
// ---------------------------------------------------------------------------
#define STR 36
#define TILE_F (128 * STR)

__device__ __forceinline__ void mma_tile(
    float* acc, const float* As, const float* Bs,
    int mw, int nw, int lr, int lc, int mode)
{
    bool sa = (mode & 1) != 0;
    bool sb = (mode & 2) != 0;
#pragma unroll
    for (int kk = 0; kk < 4; kk++) {
        int ko = kk * 8;
        unsigned bfr[4][2];
#pragma unroll
        for (int nf = 0; nf < 4; nf++) {
            const float* bp = Bs + (nw + nf * 8 + lr) * STR + ko + lc;
            unsigned u0 = __float_as_uint(bp[0]);
            unsigned u1 = __float_as_uint(bp[4]);
            bfr[nf][0] = sb ? u1 : u0;
            bfr[nf][1] = sb ? u0 : u1;
        }
#pragma unroll
        for (int mf = 0; mf < 4; mf++) {
            const float* ap = As + (mw + mf * 16 + lr) * STR + ko + lc;
            unsigned p0 = __float_as_uint(ap[0]);
            unsigned p2 = __float_as_uint(ap[4]);
            unsigned p1 = __float_as_uint(ap[8 * STR]);
            unsigned p3 = __float_as_uint(ap[8 * STR + 4]);
            unsigned a1 = sa ? p2 : p1;
            unsigned a2 = sa ? p1 : p2;
#pragma unroll
            for (int nf = 0; nf < 4; nf++) {
                float* c = acc + (mf * 4 + nf) * 4;
                mma8(c, p0, a1, a2, p3, bfr[nf][0], bfr[nf][1]);
            }
        }
    }
}

template<int CVT_OUT>
__global__ __launch_bounds__(256) void gemm_big(
    const float* __restrict__ A, const float* __restrict__ B,
    float* __restrict__ C, int M, int N, int K, float alpha,
    size_t bA, size_t bB, size_t bC)
{
    __shared__ float As[TILE_F];
    __shared__ float Bs[TILE_F];

    int mode = g_fragmode;
    int t = threadIdx.x;
    int m0 = blockIdx.y * 128, n0 = blockIdx.x * 128;
    size_t z = blockIdx.z;

    int wid = t >> 5, lane = t & 31;
    int mw = (wid & 1) * 64, nw = (wid >> 1) * 32;
    int lr = lane >> 2, lc = lane & 3;

    float acc[64];
#pragma unroll
    for (int i = 0; i < 64; i++) acc[i] = 0.f;

    int arow = t >> 3;
    int acol = (t & 7) * 4;
    const float* Ag = A + z * bA + (size_t)(m0 + arow) * K + acol;
    const float* Bg = B + z * bB + (size_t)(n0 + arow) * K + acol;

    float4 aR[4], bR[4];
    int nkt = K / 32;

#pragma unroll
    for (int r = 0; r < 4; r++) {
        aR[r] = *(const float4*)&Ag[(size_t)r * 32 * K];
        bR[r] = *(const float4*)&Bg[(size_t)r * 32 * K];
    }

    for (int kt = 0; kt < nkt; kt++) {
#pragma unroll
        for (int r = 0; r < 4; r++) {
            *(float4*)&As[(arow + 32 * r) * STR + acol] = aR[r];
            *(float4*)&Bs[(arow + 32 * r) * STR + acol] = bR[r];
        }
        __syncthreads();
        if (kt + 1 < nkt) {
            size_t go = (size_t)(kt + 1) * 32;
#pragma unroll
            for (int r = 0; r < 4; r++) {
                aR[r] = *(const float4*)&Ag[(size_t)r * 32 * K + go];
                bR[r] = *(const float4*)&Bg[(size_t)r * 32 * K + go];
            }
        }
        mma_tile(acc, As, Bs, mw, nw, lr, lc, mode);
        __syncthreads();
    }

    C += z * bC;
#pragma unroll
    for (int mf = 0; mf < 4; mf++) {
#pragma unroll
        for (int nf = 0; nf < 4; nf++) {
            float* c = acc + (mf * 4 + nf) * 4;
            int mg = m0 + mw + mf * 16 + lr;
            int ng = n0 + nw + nf * 8 + 2 * lc;
            float2 v0, v1;
            v0.x = c[0] * alpha; v0.y = c[1] * alpha;
            v1.x = c[2] * alpha; v1.y = c[3] * alpha;
            if (CVT_OUT) {
                v0.x = tf32r(v0.x); v0.y = tf32r(v0.y);
                v1.x = tf32r(v1.x); v1.y = tf32r(v1.y);
            }
            *(float2*)&C[(size_t)mg * N + ng] = v0;
            *(float2*)&C[(size_t)(mg + 8) * N + ng] = v1;
        }
    }
}

// ---------------------------------------------------------------------------
// Row softmax (round-1 proven version, verbatim).
// ---------------------------------------------------------------------------
__global__ __launch_bounds__(256) void softmax_kernel(float* __restrict__ s)
{
    size_t row = blockIdx.x;
    float4* p = (float4*)(s + row * (size_t)NTOK);
    int t = threadIdx.x;

    float4 v[4];
    float mx = -3.0e38f;
#pragma unroll
    for (int r = 0; r < 4; r++) {
        v[r] = p[r * 256 + t];
        mx = fmaxf(mx, fmaxf(fmaxf(v[r].x, v[r].y), fmaxf(v[r].z, v[r].w)));
    }
#pragma unroll
    for (int o = 16; o; o >>= 1) mx = fmaxf(mx, __shfl_xor_sync(0xffffffffu, mx, o));
    __shared__ float red[8];
    if ((t & 31) == 0) red[t >> 5] = mx;
    __syncthreads();
#pragma unroll
    for (int i = 0; i < 8; i++) mx = fmaxf(mx, red[i]);
    __syncthreads();

    float sum = 0.f;
#pragma unroll
    for (int r = 0; r < 4; r++) {
        v[r].x = __expf(v[r].x - mx);
        v[r].y = __expf(v[r].y - mx);
        v[r].z = __expf(v[r].z - mx);
        v[r].w = __expf(v[r].w - mx);
        sum += v[r].x + v[r].y + v[r].z + v[r].w;
    }
#pragma unroll
    for (int o = 16; o; o >>= 1) sum += __shfl_xor_sync(0xffffffffu, sum, o);
    if ((t & 31) == 0) red[t >> 5] = sum;
    __syncthreads();
    float tot = 0.f;
#pragma unroll
    for (int i = 0; i < 8; i++) tot += red[i];
    float inv = 1.f / tot;
#pragma unroll
    for (int r = 0; r < 4; r++) {
        v[r].x *= inv; v[r].y *= inv; v[r].z *= inv; v[r].w *= inv;
        p[r * 256 + t] = v[r];
    }
}

// ---------------------------------------------------------------------------
// kernel_launch
// ---------------------------------------------------------------------------
extern "C" void kernel_launch(void* const* d_in, const int* in_sizes, int n_in,
                              void* d_out, int out_size)
{
    const float* x   = (const float*)d_in[0];
    const float* gns = (const float*)d_in[1];
    const float* gnb = (const float*)d_in[2];
    const float* wq  = (const float*)d_in[3];
    const float* bq  = (const float*)d_in[4];
    const float* wk  = (const float*)d_in[5];
    const float* bk  = (const float*)d_in[6];
    const float* wv  = (const float*)d_in[7];
    const float* bv  = (const float*)d_in[8];
    const float* wo  = (const float*)d_in[9];
    const float* bo  = (const float*)d_in[10];
    float* out = (float*)d_out;

    float* hn = g_hn;
    float* q  = g_q;   // [ch][tok]; later reused as ao
    float* k  = g_k;
    float* v  = g_v;
    float* qT = g_qT;
    float* kT = g_kT;
    float* s  = g_s;

    // 0) self-test + GroupNorm (proven, fp32)
    mma_selftest<<<1, 32>>>();
    groupnorm_kernel<<<NB * 32, 256>>>(x, gns, gnb, hn);

    // 1) projections via proven SIMT gemm128 (M=256, N=4096, K=256)
    dim3 gp(NTOK / BN, NCH / BM, NB);
    gemm128<0, 0, 1, 0><<<gp, 256>>>(wq, hn, q, bq, nullptr,
                                     NCH, NTOK, NCH, 1.f, 1.f, 0, CHB, CHB);
    gemm128<0, 0, 1, 0><<<gp, 256>>>(wk, hn, k, bk, nullptr,
                                     NCH, NTOK, NCH, 1.f, 1.f, 0, CHB, CHB);
    gemm128<0, 0, 1, 0><<<gp, 256>>>(wv, hn, v, bv, nullptr,
                                     NCH, NTOK, NCH, 1.f, 1.f, 0, CHB, CHB);

    // 2) transpose q,k -> qT,kT  [tok][ch] (tf32-rounded)
    dim3 gt(NTOK / 32, NCH / 32, NB);
    transpose_kernel<<<gt, 256>>>(q, qT);
    transpose_kernel<<<gt, 256>>>(k, kT);

    // 3) logits s[n][m] = (1/16) qT[n,:] . kT[m,:]   (MMA under test)
    dim3 gs2(NTOK / 128, NTOK / 128, NB);
    gemm_big<0><<<gs2, 256>>>(qT, kT, s, NTOK, NTOK, NCH, 0.0625f,
                              CHB, CHB, NNB);

    // 4) softmax (proven, fp32)
    softmax_kernel<<<NB * NTOK, 256>>>(s);

    // 5) ao[c][n] = v[c,:] . att[n,:]  (MMA under test) -> reuse g_q
    dim3 gav(NTOK / 128, NCH / 128, NB);
    gemm_big<0><<<gav, 256>>>(v, s, q, NCH, NTOK, NTOK, 1.f,
                              CHB, NNB, CHB);

    // 6) final projection + residual via proven gemm128 (exact fp32 weights)
    gemm128<0, 0, 1, 1><<<gp, 256>>>(wo, q, out, bo, x,
                                     NCH, NTOK, NCH, 1.f, 0.70710678118654752f,
                                     0, CHB, CHB);
}

// round 7
// speedup vs baseline: 39.3780x; 39.3780x over previous
#include <cuda_runtime.h>
#include <cuda_bf16.h>
#include <cstdint>
#include <cstddef>

// Problem constants
#define NB    8
#define NCH   256
#define NTOK  4096
#define CHB   ((size_t)NCH * NTOK)
#define NNB   ((size_t)NTOK * NTOK)

typedef __nv_bfloat16 bf16;

// Static scratch — accessed ONLY via cudaGetSymbolAddress-resolved pointers.
__device__ __align__(256) float g_hn [NB * CHB];   // groupnorm out fp32 [ch][tok]
__device__ __align__(256) bf16  g_hnT[NB * CHB];   // [tok][ch]
__device__ __align__(256) bf16  g_qT [NB * CHB];   // [tok][ch]
__device__ __align__(256) bf16  g_kT [NB * CHB];   // [tok][ch]
__device__ __align__(256) bf16  g_v  [NB * CHB];   // [ch][tok]
__device__ __align__(256) bf16  g_aoT[NB * CHB];   // [tok][ch]
__device__ __align__(256) float g_s  [NB * NNB];   // logits fp32
__device__ __align__(256) bf16  g_att[NB * NNB];   // probs bf16
__device__ __align__(256) bf16  g_wb [4 * NCH * NCH]; // bf16 weights q,k,v,o

// ---------------------------------------------------------------------------
// prep: weights fp32 -> bf16 (writes via passed pointer — consistent path)
// ---------------------------------------------------------------------------
__global__ __launch_bounds__(256) void prep_kernel(
    const float* __restrict__ wq, const float* __restrict__ wk,
    const float* __restrict__ wv, const float* __restrict__ wo,
    bf16* __restrict__ wb)
{
    int i = blockIdx.x * 256 + threadIdx.x;  // 65536
    wb[i]          = __float2bfloat16(wq[i]);
    wb[ 65536 + i] = __float2bfloat16(wk[i]);
    wb[131072 + i] = __float2bfloat16(wv[i]);
    wb[196608 + i] = __float2bfloat16(wo[i]);
}

// ---------------------------------------------------------------------------
// GroupNorm (round-1 proven, fp32 out)
// ---------------------------------------------------------------------------
__global__ __launch_bounds__(256) void groupnorm_kernel(
    const float* __restrict__ x, const float* __restrict__ sc,
    const float* __restrict__ bi, float* __restrict__ out)
{
    int b = blockIdx.x >> 5;
    int g = blockIdx.x & 31;
    size_t base = ((size_t)b * NCH + (size_t)g * 8) * NTOK;
    const float4* px = (const float4*)(x + base);
    float4* po = (float4*)(out + base);
    int t = threadIdx.x;

    float s = 0.f, ss = 0.f;
#pragma unroll
    for (int r = 0; r < 32; r++) {
        float4 f = px[r * 256 + t];
        s  += f.x + f.y + f.z + f.w;
        ss += f.x * f.x + f.y * f.y + f.z * f.z + f.w * f.w;
    }
#pragma unroll
    for (int o = 16; o; o >>= 1) {
        s  += __shfl_xor_sync(0xffffffffu, s, o);
        ss += __shfl_xor_sync(0xffffffffu, ss, o);
    }
    __shared__ float rs[8], rss[8];
    __shared__ float s_mean, s_rstd;
    if ((t & 31) == 0) { rs[t >> 5] = s; rss[t >> 5] = ss; }
    __syncthreads();
    if (t == 0) {
        float S = 0.f, SS = 0.f;
#pragma unroll
        for (int i = 0; i < 8; i++) { S += rs[i]; SS += rss[i]; }
        float m = S * (1.f / 32768.f);
        float var = SS * (1.f / 32768.f) - m * m;
        s_mean = m;
        s_rstd = rsqrtf(var + 1e-6f);
    }
    __syncthreads();
    float m = s_mean, rstd = s_rstd;
#pragma unroll
    for (int r = 0; r < 32; r++) {
        int idx = r * 256 + t;
        int c = g * 8 + (idx >> 10);
        float a = sc[c] * rstd;
        float bb = bi[c] - m * a;
        float4 f = px[idx];
        po[idx] = make_float4(f.x * a + bb, f.y * a + bb, f.z * a + bb, f.w * a + bb);
    }
}

// ---------------------------------------------------------------------------
// Transpose hn [256][4096] fp32 -> hnT [4096][256] bf16
// ---------------------------------------------------------------------------
__global__ __launch_bounds__(256) void transpose_bf16_kernel(
    const float* __restrict__ in, bf16* __restrict__ out)
{
    __shared__ float tile[32][33];
    size_t z = blockIdx.z;
    const float* ip = in + z * CHB;
    bf16* op = out + z * CHB;
    int n0 = blockIdx.x * 32, c0 = blockIdx.y * 32;
    int tx = threadIdx.x & 31, ty = threadIdx.x >> 5;
#pragma unroll
    for (int j = 0; j < 32; j += 8)
        tile[ty + j][tx] = ip[(size_t)(c0 + ty + j) * NTOK + n0 + tx];
    __syncthreads();
#pragma unroll
    for (int j = 0; j < 32; j += 8)
        op[(size_t)(n0 + ty + j) * NCH + c0 + tx] = __float2bfloat16(tile[tx][ty + j]);
}

// ---------------------------------------------------------------------------
// Warp-MMA bf16 GEMM:  C[m][n] = alpha * sum_k A[m][k]*B[n][k] (+bias)(+resid)*outscale
// A: [M][K] bf16 row-major, B: [N][K] bf16 row-major.
// Tile 128x128, 8 warps (2x4), warp tile 64x32, K-chunk 32 bf16.
// BIAS_MODE: 0 none, 1 per-row bias[m], 2 per-col bias[n].
// ---------------------------------------------------------------------------
#define ASTRB 40   // bf16 stride: 32 K + 8 pad

__device__ __forceinline__ void mma16816(float* c, unsigned a0, unsigned a1,
                                         unsigned a2, unsigned a3,
                                         unsigned b0, unsigned b1)
{
    asm volatile(
        "mma.sync.aligned.m16n8k16.row.col.f32.bf16.bf16.f32 "
        "{%0,%1,%2,%3},{%4,%5,%6,%7},{%8,%9},{%0,%1,%2,%3};"
        : "+f"(c[0]), "+f"(c[1]), "+f"(c[2]), "+f"(c[3])
        : "r"(a0), "r"(a1), "r"(a2), "r"(a3), "r"(b0), "r"(b1));
}

template<int OUT_BF16, int BIAS_MODE, int RESID>
__global__ __launch_bounds__(256) void hgemm(
    const bf16* __restrict__ A, const bf16* __restrict__ B,
    void* __restrict__ Cout, const float* __restrict__ bias,
    const float* __restrict__ resid, float alpha, float outscale,
    int M, int N, int K, size_t bA, size_t bB, size_t bC)
{
    __shared__ bf16 As[128 * ASTRB];
    __shared__ bf16 Bs[128 * ASTRB];

    int t = threadIdx.x;
    int m0 = blockIdx.y * 128, n0 = blockIdx.x * 128;
    size_t z = blockIdx.z;

    int wid = t >> 5, lane = t & 31;
    int mw = (wid & 1) * 64, nw = (wid >> 1) * 32;
    int lr = lane >> 2, lc = lane & 3;

    float acc[64];
#pragma unroll
    for (int i = 0; i < 64; i++) acc[i] = 0.f;

    // staging map: thread t covers rows rowa and rowa+64, granule g (8 bf16)
    int rowa = t >> 2, g = t & 3;
    const bf16* Ab = A + z * bA;
    const bf16* Bb = B + z * bB;

    float4 aR[2], bR[2];
    int nkt = K / 32;

#pragma unroll
    for (int r = 0; r < 2; r++) {
        aR[r] = *(const float4*)&Ab[(size_t)(m0 + rowa + 64 * r) * K + g * 8];
        bR[r] = *(const float4*)&Bb[(size_t)(n0 + rowa + 64 * r) * K + g * 8];
    }

    for (int kt = 0; kt < nkt; kt++) {
#pragma unroll
        for (int r = 0; r < 2; r++) {
            *(float4*)&As[(rowa + 64 * r) * ASTRB + g * 8] = aR[r];
            *(float4*)&Bs[(rowa + 64 * r) * ASTRB + g * 8] = bR[r];
        }
        __syncthreads();
        if (kt + 1 < nkt) {
            size_t ko = (size_t)(kt + 1) * 32;
#pragma unroll
            for (int r = 0; r < 2; r++) {
                aR[r] = *(const float4*)&Ab[(size_t)(m0 + rowa + 64 * r) * K + ko + g * 8];
                bR[r] = *(const float4*)&Bb[(size_t)(n0 + rowa + 64 * r) * K + ko + g * 8];
            }
        }
#pragma unroll
        for (int ks = 0; ks < 2; ks++) {
            int ko = ks * 16;
            unsigned bfr[4][2];
#pragma unroll
            for (int nf = 0; nf < 4; nf++) {
                const bf16* bp = Bs + (nw + nf * 8 + lr) * ASTRB + ko + 2 * lc;
                bfr[nf][0] = *(const unsigned*)bp;
                bfr[nf][1] = *(const unsigned*)(bp + 8);
            }
#pragma unroll
            for (int mf = 0; mf < 4; mf++) {
                const bf16* ap = As + (mw + mf * 16 + lr) * ASTRB + ko + 2 * lc;
                unsigned a0 = *(const unsigned*)ap;
                unsigned a1 = *(const unsigned*)(ap + 8 * ASTRB);
                unsigned a2 = *(const unsigned*)(ap + 8);
                unsigned a3 = *(const unsigned*)(ap + 8 * ASTRB + 8);
#pragma unroll
                for (int nf = 0; nf < 4; nf++)
                    mma16816(acc + (mf * 4 + nf) * 4, a0, a1, a2, a3,
                             bfr[nf][0], bfr[nf][1]);
            }
        }
        __syncthreads();
    }

    // epilogue
#pragma unroll
    for (int mf = 0; mf < 4; mf++) {
#pragma unroll
        for (int nf = 0; nf < 4; nf++) {
            float* c = acc + (mf * 4 + nf) * 4;
            int mg = m0 + mw + mf * 16 + lr;
            int ng = n0 + nw + nf * 8 + 2 * lc;
            float o0 = c[0] * alpha, o1 = c[1] * alpha;
            float o2 = c[2] * alpha, o3 = c[3] * alpha;
            if (BIAS_MODE == 1) {
                float b0 = bias[mg], b1 = bias[mg + 8];
                o0 += b0; o1 += b0; o2 += b1; o3 += b1;
            } else if (BIAS_MODE == 2) {
                float b0 = bias[ng], b1 = bias[ng + 1];
                o0 += b0; o1 += b1; o2 += b0; o3 += b1;
            }
            size_t i0 = (size_t)mg * N + ng;
            size_t i1 = (size_t)(mg + 8) * N + ng;
            if (RESID) {
                const float* Rb = resid + z * bC;
                o0 = (o0 + Rb[i0])     * outscale;
                o1 = (o1 + Rb[i0 + 1]) * outscale;
                o2 = (o2 + Rb[i1])     * outscale;
                o3 = (o3 + Rb[i1 + 1]) * outscale;
            }
            if (OUT_BF16) {
                bf16* Cb = (bf16*)Cout + z * bC;
                __nv_bfloat162 h0 = __floats2bfloat162_rn(o0, o1);
                __nv_bfloat162 h1 = __floats2bfloat162_rn(o2, o3);
                *(uint32_t*)&Cb[i0] = *(uint32_t*)&h0;
                *(uint32_t*)&Cb[i1] = *(uint32_t*)&h1;
            } else {
                float* Cb = (float*)Cout + z * bC;
                float2 p0 = {o0, o1}, p1 = {o2, o3};
                *(float2*)&Cb[i0] = p0;
                *(float2*)&Cb[i1] = p1;
            }
        }
    }
}

// ---------------------------------------------------------------------------
// Softmax rows (fp32 in, bf16 out), polynomial exp on the FFMA pipe.
// ---------------------------------------------------------------------------
__device__ __forceinline__ float fexp(float x) {  // x <= 0
    float zc = fmaxf(x * 1.4426950408889634f, -126.0f);
    float r = zc + 12582912.0f;
    float zi = r - 12582912.0f;
    float f = zc - zi;
    int e = (__float_as_int(r) & 0x7FFFFF) - 0x400000;
    float p = 1.3333558e-3f;
    p = fmaf(p, f, 9.6181291e-3f);
    p = fmaf(p, f, 5.5504109e-2f);
    p = fmaf(p, f, 2.4022651e-1f);
    p = fmaf(p, f, 6.9314718e-1f);
    p = fmaf(p, f, 1.0f);
    return __int_as_float((e + 127) << 23) * p;
}

__global__ __launch_bounds__(256) void softmax_bf16_kernel(
    const float* __restrict__ s, bf16* __restrict__ att)
{
    size_t row = blockIdx.x;
    const float4* p = (const float4*)(s + row * (size_t)NTOK);
    uint32_t* q = (uint32_t*)(att + row * (size_t)NTOK);
    int t = threadIdx.x;

    float4 v[4];
    float mx = -3.0e38f;
#pragma unroll
    for (int r = 0; r < 4; r++) {
        v[r] = p[r * 256 + t];
        mx = fmaxf(mx, fmaxf(fmaxf(v[r].x, v[r].y), fmaxf(v[r].z, v[r].w)));
    }
#pragma unroll
    for (int o = 16; o; o >>= 1) mx = fmaxf(mx, __shfl_xor_sync(0xffffffffu, mx, o));
    __shared__ float red[8];
    if ((t & 31) == 0) red[t >> 5] = mx;
    __syncthreads();
#pragma unroll
    for (int i = 0; i < 8; i++) mx = fmaxf(mx, red[i]);
    __syncthreads();

    float sum = 0.f;
#pragma unroll
    for (int r = 0; r < 4; r++) {
        v[r].x = fexp(v[r].x - mx);
        v[r].y = fexp(v[r].y - mx);
        v[r].z = fexp(v[r].z - mx);
        v[r].w = fexp(v[r].w - mx);
        sum += v[r].x + v[r].y + v[r].z + v[r].w;
    }
#pragma unroll
    for (int o = 16; o; o >>= 1) sum += __shfl_xor_sync(0xffffffffu, sum, o);
    if ((t & 31) == 0) red[t >> 5] = sum;
    __syncthreads();
    float tot = 0.f;
#pragma unroll
    for (int i = 0; i < 8; i++) tot += red[i];
    float inv = 1.f / tot;
#pragma unroll
    for (int r = 0; r < 4; r++) {
        __nv_bfloat162 h0 = __floats2bfloat162_rn(v[r].x * inv, v[r].y * inv);
        __nv_bfloat162 h1 = __floats2bfloat162_rn(v[r].z * inv, v[r].w * inv);
        q[(r * 256 + t) * 2]     = *(uint32_t*)&h0;
        q[(r * 256 + t) * 2 + 1] = *(uint32_t*)&h1;
    }
}

// ---------------------------------------------------------------------------
// kernel_launch — all scratch resolved via cudaGetSymbolAddress (TRUE device
// addresses; the host-shadow addresses of __device__ vars resolve into
// zero-filled host memory through ATS on GB300 — the rounds-2/3/6 bug).
// ---------------------------------------------------------------------------
extern "C" void kernel_launch(void* const* d_in, const int* in_sizes, int n_in,
                              void* d_out, int out_size)
{
    const float* x   = (const float*)d_in[0];
    const float* gns = (const float*)d_in[1];
    const float* gnb = (const float*)d_in[2];
    const float* wq  = (const float*)d_in[3];
    const float* bq  = (const float*)d_in[4];
    const float* wk  = (const float*)d_in[5];
    const float* bk  = (const float*)d_in[6];
    const float* wv  = (const float*)d_in[7];
    const float* bv  = (const float*)d_in[8];
    const float* wo  = (const float*)d_in[9];
    const float* bo  = (const float*)d_in[10];
    float* out = (float*)d_out;

    void *p_hn, *p_hnT, *p_qT, *p_kT, *p_v, *p_aoT, *p_s, *p_att, *p_wb;
    cudaGetSymbolAddress(&p_hn,  g_hn);
    cudaGetSymbolAddress(&p_hnT, g_hnT);
    cudaGetSymbolAddress(&p_qT,  g_qT);
    cudaGetSymbolAddress(&p_kT,  g_kT);
    cudaGetSymbolAddress(&p_v,   g_v);
    cudaGetSymbolAddress(&p_aoT, g_aoT);
    cudaGetSymbolAddress(&p_s,   g_s);
    cudaGetSymbolAddress(&p_att, g_att);
    cudaGetSymbolAddress(&p_wb,  g_wb);
    float* hn  = (float*)p_hn;
    bf16*  hnT = (bf16*)p_hnT;
    bf16*  qT  = (bf16*)p_qT;
    bf16*  kT  = (bf16*)p_kT;
    bf16*  v   = (bf16*)p_v;
    bf16*  aoT = (bf16*)p_aoT;
    float* s   = (float*)p_s;
    bf16*  att = (bf16*)p_att;
    bf16*  wb  = (bf16*)p_wb;

    // 0) bf16 weights + GroupNorm + hnT
    prep_kernel<<<256, 256>>>(wq, wk, wv, wo, wb);
    groupnorm_kernel<<<NB * 32, 256>>>(x, gns, gnb, hn);
    transpose_bf16_kernel<<<dim3(NTOK / 32, NCH / 32, NB), 256>>>(hn, hnT);

    // 1) qT[tok][ch] = hnT . wq^T + bq (per-col); kT likewise
    hgemm<1, 2, 0><<<dim3(2, 32, NB), 256>>>(
        hnT, wb, qT, bq, nullptr, 1.f, 1.f,
        NTOK, NCH, NCH, CHB, 0, CHB);
    hgemm<1, 2, 0><<<dim3(2, 32, NB), 256>>>(
        hnT, wb + 65536, kT, bk, nullptr, 1.f, 1.f,
        NTOK, NCH, NCH, CHB, 0, CHB);
    // v[ch][tok] = wv . hnT^T + bv (per-row)
    hgemm<1, 1, 0><<<dim3(32, 2, NB), 256>>>(
        wb + 131072, hnT, v, bv, nullptr, 1.f, 1.f,
        NCH, NTOK, NCH, 0, CHB, CHB);

    // 2) logits s[q][k] = (1/16) qT . kT^T   (fp32 out)
    hgemm<0, 0, 0><<<dim3(32, 32, NB), 256>>>(
        qT, kT, s, nullptr, nullptr, 0.0625f, 1.f,
        NTOK, NTOK, NCH, CHB, CHB, NNB);

    // 3) softmax rows -> bf16 att
    softmax_bf16_kernel<<<NB * NTOK, 256>>>(s, att);

    // 4) aoT[q][ch] = att . v^T
    hgemm<1, 0, 0><<<dim3(2, 32, NB), 256>>>(
        att, v, aoT, nullptr, nullptr, 1.f, 1.f,
        NTOK, NCH, NTOK, NNB, CHB, CHB);

    // 5) out[ch][tok] = (wo . aoT^T + bo + x) / sqrt(2)
    hgemm<0, 1, 1><<<dim3(32, 2, NB), 256>>>(
        wb + 196608, aoT, out, bo, x, 1.f, 0.70710678118654752f,
        NCH, NTOK, NCH, 0, CHB, CHB);
}

// round 8
// speedup vs baseline: 46.9440x; 1.1921x over previous
#include <cuda_runtime.h>
#include <cuda_bf16.h>
#include <cstdint>
#include <cstddef>

// Problem constants
#define NB    8
#define NCH   256
#define NTOK  4096
#define CHB   ((size_t)NCH * NTOK)
#define NNB   ((size_t)NTOK * NTOK)

typedef __nv_bfloat16 bf16;

// Static scratch — accessed ONLY via cudaGetSymbolAddress-resolved pointers.
__device__ __align__(256) float g_hn [NB * CHB];   // groupnorm out fp32 [ch][tok]
__device__ __align__(256) bf16  g_hnT[NB * CHB];   // [tok][ch]
__device__ __align__(256) bf16  g_qT [NB * CHB];   // [tok][ch]
__device__ __align__(256) bf16  g_kT [NB * CHB];   // [tok][ch]
__device__ __align__(256) bf16  g_v  [NB * CHB];   // [ch][tok]
__device__ __align__(256) bf16  g_aoT[NB * CHB];   // [tok][ch]
__device__ __align__(256) float g_s  [NB * NNB];   // logits fp32
__device__ __align__(256) bf16  g_att[NB * NNB];   // probs bf16
__device__ __align__(256) bf16  g_wb [4 * NCH * NCH]; // bf16 weights q,k,v,o

// ---------------------------------------------------------------------------
// prep: weights fp32 -> bf16
// ---------------------------------------------------------------------------
__global__ __launch_bounds__(256) void prep_kernel(
    const float* __restrict__ wq, const float* __restrict__ wk,
    const float* __restrict__ wv, const float* __restrict__ wo,
    bf16* __restrict__ wb)
{
    int i = blockIdx.x * 256 + threadIdx.x;  // 65536
    wb[i]          = __float2bfloat16(wq[i]);
    wb[ 65536 + i] = __float2bfloat16(wk[i]);
    wb[131072 + i] = __float2bfloat16(wv[i]);
    wb[196608 + i] = __float2bfloat16(wo[i]);
}

// ---------------------------------------------------------------------------
// GroupNorm (proven, fp32 out)
// ---------------------------------------------------------------------------
__global__ __launch_bounds__(256) void groupnorm_kernel(
    const float* __restrict__ x, const float* __restrict__ sc,
    const float* __restrict__ bi, float* __restrict__ out)
{
    int b = blockIdx.x >> 5;
    int g = blockIdx.x & 31;
    size_t base = ((size_t)b * NCH + (size_t)g * 8) * NTOK;
    const float4* px = (const float4*)(x + base);
    float4* po = (float4*)(out + base);
    int t = threadIdx.x;

    float s = 0.f, ss = 0.f;
#pragma unroll
    for (int r = 0; r < 32; r++) {
        float4 f = px[r * 256 + t];
        s  += f.x + f.y + f.z + f.w;
        ss += f.x * f.x + f.y * f.y + f.z * f.z + f.w * f.w;
    }
#pragma unroll
    for (int o = 16; o; o >>= 1) {
        s  += __shfl_xor_sync(0xffffffffu, s, o);
        ss += __shfl_xor_sync(0xffffffffu, ss, o);
    }
    __shared__ float rs[8], rss[8];
    __shared__ float s_mean, s_rstd;
    if ((t & 31) == 0) { rs[t >> 5] = s; rss[t >> 5] = ss; }
    __syncthreads();
    if (t == 0) {
        float S = 0.f, SS = 0.f;
#pragma unroll
        for (int i = 0; i < 8; i++) { S += rs[i]; SS += rss[i]; }
        float m = S * (1.f / 32768.f);
        float var = SS * (1.f / 32768.f) - m * m;
        s_mean = m;
        s_rstd = rsqrtf(var + 1e-6f);
    }
    __syncthreads();
    float m = s_mean, rstd = s_rstd;
#pragma unroll
    for (int r = 0; r < 32; r++) {
        int idx = r * 256 + t;
        int c = g * 8 + (idx >> 10);
        float a = sc[c] * rstd;
        float bb = bi[c] - m * a;
        float4 f = px[idx];
        po[idx] = make_float4(f.x * a + bb, f.y * a + bb, f.z * a + bb, f.w * a + bb);
    }
}

// ---------------------------------------------------------------------------
// Transpose hn [256][4096] fp32 -> hnT [4096][256] bf16
// ---------------------------------------------------------------------------
__global__ __launch_bounds__(256) void transpose_bf16_kernel(
    const float* __restrict__ in, bf16* __restrict__ out)
{
    __shared__ float tile[32][33];
    size_t z = blockIdx.z;
    const float* ip = in + z * CHB;
    bf16* op = out + z * CHB;
    int n0 = blockIdx.x * 32, c0 = blockIdx.y * 32;
    int tx = threadIdx.x & 31, ty = threadIdx.x >> 5;
#pragma unroll
    for (int j = 0; j < 32; j += 8)
        tile[ty + j][tx] = ip[(size_t)(c0 + ty + j) * NTOK + n0 + tx];
    __syncthreads();
#pragma unroll
    for (int j = 0; j < 32; j += 8)
        op[(size_t)(n0 + ty + j) * NCH + c0 + tx] = __float2bfloat16(tile[tx][ty + j]);
}

// ---------------------------------------------------------------------------
// Warp-MMA bf16 GEMM (ldmatrix + cp.async double buffer).
// C[m][n] = alpha * sum_k A[m][k]*B[n][k] (+bias)(+resid)*outscale
// A: [M][K] bf16 row-major, B: [N][K] bf16 row-major.
// Tile 128x128, 8 warps (2x4), warp tile 64x32, K-chunk 32.
// BIAS_MODE: 0 none, 1 per-row bias[m], 2 per-col bias[n].
// ---------------------------------------------------------------------------
#define ASTRB 40   // bf16 row stride: 80B -> ldmatrix conflict-free (5 coprime 8)

__device__ __forceinline__ void mma16816(float* c, unsigned a0, unsigned a1,
                                         unsigned a2, unsigned a3,
                                         unsigned b0, unsigned b1)
{
    asm volatile(
        "mma.sync.aligned.m16n8k16.row.col.f32.bf16.bf16.f32 "
        "{%0,%1,%2,%3},{%4,%5,%6,%7},{%8,%9},{%0,%1,%2,%3};"
        : "+f"(c[0]), "+f"(c[1]), "+f"(c[2]), "+f"(c[3])
        : "r"(a0), "r"(a1), "r"(a2), "r"(a3), "r"(b0), "r"(b1));
}

#define LDSM4(r0, r1, r2, r3, addr) \
    asm volatile("ldmatrix.sync.aligned.m8n8.x4.shared.b16 {%0,%1,%2,%3}, [%4];" \
                 : "=r"(r0), "=r"(r1), "=r"(r2), "=r"(r3) : "r"(addr))

#define CP16(dst, src) \
    asm volatile("cp.async.cg.shared.global [%0], [%1], 16;" :: "r"(dst), "l"(src))

template<int OUT_BF16, int BIAS_MODE, int RESID>
__global__ __launch_bounds__(256, 2) void hgemm(
    const bf16* __restrict__ A, const bf16* __restrict__ B,
    void* __restrict__ Cout, const float* __restrict__ bias,
    const float* __restrict__ resid, float alpha, float outscale,
    int M, int N, int K, size_t bA, size_t bB, size_t bC)
{
    __shared__ bf16 As[2][128 * ASTRB];
    __shared__ bf16 Bs[2][128 * ASTRB];

    int t = threadIdx.x;
    int m0 = blockIdx.y * 128, n0 = blockIdx.x * 128;
    size_t z = blockIdx.z;

    int wid = t >> 5, lane = t & 31;
    int mw = (wid & 1) * 64, nw = (wid >> 1) * 32;
    int lr = lane >> 2, lc = lane & 3;

    float acc[64];
#pragma unroll
    for (int i = 0; i < 64; i++) acc[i] = 0.f;

    // cp.async staging map: thread t -> rows (t>>2) and (t>>2)+64, 16B granule t&3
    int rowa = t >> 2, gcol = t & 3;
    const bf16* Ab = A + z * bA + (size_t)(m0 + rowa) * K + gcol * 8;
    const bf16* Bb = B + z * bB + (size_t)(n0 + rowa) * K + gcol * 8;
    size_t rstep = (size_t)64 * K;

    uint32_t aBase = (uint32_t)__cvta_generic_to_shared(&As[0][0]);
    uint32_t bBase = (uint32_t)__cvta_generic_to_shared(&Bs[0][0]);
    const uint32_t BUFB = 128 * ASTRB * 2;  // bytes per buffer
    uint32_t stOff = (uint32_t)(rowa * ASTRB + gcol * 8) * 2;
    uint32_t stOff64 = stOff + (uint32_t)(64 * ASTRB) * 2;

    // ldmatrix lane maps
    // A x4 slabs: (m0-7,k0),(m8-15,k0),(m0-7,k8),(m8-15,k8)
    int arow_l = (lane & 7) + ((lane >> 3) & 1) * 8;  // 0..15
    int akof_l = (lane >> 4) * 8;                     // 0 or 8
    // B x4 slabs: (n0-7,k0),(n0-7,k8),(n8-15,k0),(n8-15,k8)
    int brow_l = (lane & 7) + ((lane >> 4) & 1) * 8;
    int bkof_l = ((lane >> 3) & 1) * 8;

    int nkt = K / 32;

    // prologue: stage chunk 0 into buffer 0
    {
        CP16(aBase + stOff,   Ab);
        CP16(aBase + stOff64, Ab + rstep);
        CP16(bBase + stOff,   Bb);
        CP16(bBase + stOff64, Bb + rstep);
        asm volatile("cp.async.commit_group;" ::: "memory");
    }

    for (int kt = 0; kt < nkt; kt++) {
        if (kt + 1 < nkt) {
            size_t go = (size_t)(kt + 1) * 32;
            uint32_t so = ((kt + 1) & 1) * BUFB;
            CP16(aBase + so + stOff,   Ab + go);
            CP16(aBase + so + stOff64, Ab + go + rstep);
            CP16(bBase + so + stOff,   Bb + go);
            CP16(bBase + so + stOff64, Bb + go + rstep);
            asm volatile("cp.async.commit_group;" ::: "memory");
            asm volatile("cp.async.wait_group 1;" ::: "memory");
        } else {
            asm volatile("cp.async.wait_group 0;" ::: "memory");
        }
        __syncthreads();

        uint32_t aBuf = aBase + (kt & 1) * BUFB;
        uint32_t bBuf = bBase + (kt & 1) * BUFB;
#pragma unroll
        for (int ks = 0; ks < 2; ks++) {
            int ko = ks * 16;
            unsigned bfr[4][2];
#pragma unroll
            for (int np = 0; np < 2; np++) {  // nf pairs {0,1}, {2,3}
                uint32_t ba = bBuf + (uint32_t)((nw + np * 16 + brow_l) * ASTRB
                                                + ko + bkof_l) * 2;
                LDSM4(bfr[np * 2][0], bfr[np * 2][1],
                      bfr[np * 2 + 1][0], bfr[np * 2 + 1][1], ba);
            }
#pragma unroll
            for (int mf = 0; mf < 4; mf++) {
                unsigned a0, a1, a2, a3;
                uint32_t aa = aBuf + (uint32_t)((mw + mf * 16 + arow_l) * ASTRB
                                                + ko + akof_l) * 2;
                LDSM4(a0, a1, a2, a3, aa);
#pragma unroll
                for (int nf = 0; nf < 4; nf++)
                    mma16816(acc + (mf * 4 + nf) * 4, a0, a1, a2, a3,
                             bfr[nf][0], bfr[nf][1]);
            }
        }
        __syncthreads();
    }

    // epilogue
#pragma unroll
    for (int mf = 0; mf < 4; mf++) {
#pragma unroll
        for (int nf = 0; nf < 4; nf++) {
            float* c = acc + (mf * 4 + nf) * 4;
            int mg = m0 + mw + mf * 16 + lr;
            int ng = n0 + nw + nf * 8 + 2 * lc;
            float o0 = c[0] * alpha, o1 = c[1] * alpha;
            float o2 = c[2] * alpha, o3 = c[3] * alpha;
            if (BIAS_MODE == 1) {
                float b0 = bias[mg], b1 = bias[mg + 8];
                o0 += b0; o1 += b0; o2 += b1; o3 += b1;
            } else if (BIAS_MODE == 2) {
                float b0 = bias[ng], b1 = bias[ng + 1];
                o0 += b0; o1 += b1; o2 += b0; o3 += b1;
            }
            size_t i0 = (size_t)mg * N + ng;
            size_t i1 = (size_t)(mg + 8) * N + ng;
            if (RESID) {
                const float* Rb = resid + z * bC;
                o0 = (o0 + Rb[i0])     * outscale;
                o1 = (o1 + Rb[i0 + 1]) * outscale;
                o2 = (o2 + Rb[i1])     * outscale;
                o3 = (o3 + Rb[i1 + 1]) * outscale;
            }
            if (OUT_BF16) {
                bf16* Cb = (bf16*)Cout + z * bC;
                __nv_bfloat162 h0 = __floats2bfloat162_rn(o0, o1);
                __nv_bfloat162 h1 = __floats2bfloat162_rn(o2, o3);
                *(uint32_t*)&Cb[i0] = *(uint32_t*)&h0;
                *(uint32_t*)&Cb[i1] = *(uint32_t*)&h1;
            } else {
                float* Cb = (float*)Cout + z * bC;
                float2 p0 = {o0, o1}, p1 = {o2, o3};
                *(float2*)&Cb[i0] = p0;
                *(float2*)&Cb[i1] = p1;
            }
        }
    }
}

// ---------------------------------------------------------------------------
// Softmax rows (fp32 in, bf16 out), polynomial exp on the FFMA pipe.
// ---------------------------------------------------------------------------
__device__ __forceinline__ float fexp(float x) {  // x <= 0
    float zc = fmaxf(x * 1.4426950408889634f, -126.0f);
    float r = zc + 12582912.0f;
    float zi = r - 12582912.0f;
    float f = zc - zi;
    int e = (__float_as_int(r) & 0x7FFFFF) - 0x400000;
    float p = 1.3333558e-3f;
    p = fmaf(p, f, 9.6181291e-3f);
    p = fmaf(p, f, 5.5504109e-2f);
    p = fmaf(p, f, 2.4022651e-1f);
    p = fmaf(p, f, 6.9314718e-1f);
    p = fmaf(p, f, 1.0f);
    return __int_as_float((e + 127) << 23) * p;
}

__global__ __launch_bounds__(256) void softmax_bf16_kernel(
    const float* __restrict__ s, bf16* __restrict__ att)
{
    size_t row = blockIdx.x;
    const float4* p = (const float4*)(s + row * (size_t)NTOK);
    uint32_t* q = (uint32_t*)(att + row * (size_t)NTOK);
    int t = threadIdx.x;

    float4 v[4];
    float mx = -3.0e38f;
#pragma unroll
    for (int r = 0; r < 4; r++) {
        v[r] = p[r * 256 + t];
        mx = fmaxf(mx, fmaxf(fmaxf(v[r].x, v[r].y), fmaxf(v[r].z, v[r].w)));
    }
#pragma unroll
    for (int o = 16; o; o >>= 1) mx = fmaxf(mx, __shfl_xor_sync(0xffffffffu, mx, o));
    __shared__ float red[8];
    if ((t & 31) == 0) red[t >> 5] = mx;
    __syncthreads();
#pragma unroll
    for (int i = 0; i < 8; i++) mx = fmaxf(mx, red[i]);
    __syncthreads();

    float sum = 0.f;
#pragma unroll
    for (int r = 0; r < 4; r++) {
        v[r].x = fexp(v[r].x - mx);
        v[r].y = fexp(v[r].y - mx);
        v[r].z = fexp(v[r].z - mx);
        v[r].w = fexp(v[r].w - mx);
        sum += v[r].x + v[r].y + v[r].z + v[r].w;
    }
#pragma unroll
    for (int o = 16; o; o >>= 1) sum += __shfl_xor_sync(0xffffffffu, sum, o);
    if ((t & 31) == 0) red[t >> 5] = sum;
    __syncthreads();
    float tot = 0.f;
#pragma unroll
    for (int i = 0; i < 8; i++) tot += red[i];
    float inv = 1.f / tot;
#pragma unroll
    for (int r = 0; r < 4; r++) {
        __nv_bfloat162 h0 = __floats2bfloat162_rn(v[r].x * inv, v[r].y * inv);
        __nv_bfloat162 h1 = __floats2bfloat162_rn(v[r].z * inv, v[r].w * inv);
        q[(r * 256 + t) * 2]     = *(uint32_t*)&h0;
        q[(r * 256 + t) * 2 + 1] = *(uint32_t*)&h1;
    }
}

// ---------------------------------------------------------------------------
// kernel_launch — scratch via cudaGetSymbolAddress (true device addresses).
// ---------------------------------------------------------------------------
extern "C" void kernel_launch(void* const* d_in, const int* in_sizes, int n_in,
                              void* d_out, int out_size)
{
    const float* x   = (const float*)d_in[0];
    const float* gns = (const float*)d_in[1];
    const float* gnb = (const float*)d_in[2];
    const float* wq  = (const float*)d_in[3];
    const float* bq  = (const float*)d_in[4];
    const float* wk  = (const float*)d_in[5];
    const float* bk  = (const float*)d_in[6];
    const float* wv  = (const float*)d_in[7];
    const float* bv  = (const float*)d_in[8];
    const float* wo  = (const float*)d_in[9];
    const float* bo  = (const float*)d_in[10];
    float* out = (float*)d_out;

    void *p_hn, *p_hnT, *p_qT, *p_kT, *p_v, *p_aoT, *p_s, *p_att, *p_wb;
    cudaGetSymbolAddress(&p_hn,  g_hn);
    cudaGetSymbolAddress(&p_hnT, g_hnT);
    cudaGetSymbolAddress(&p_qT,  g_qT);
    cudaGetSymbolAddress(&p_kT,  g_kT);
    cudaGetSymbolAddress(&p_v,   g_v);
    cudaGetSymbolAddress(&p_aoT, g_aoT);
    cudaGetSymbolAddress(&p_s,   g_s);
    cudaGetSymbolAddress(&p_att, g_att);
    cudaGetSymbolAddress(&p_wb,  g_wb);
    float* hn  = (float*)p_hn;
    bf16*  hnT = (bf16*)p_hnT;
    bf16*  qT  = (bf16*)p_qT;
    bf16*  kT  = (bf16*)p_kT;
    bf16*  v   = (bf16*)p_v;
    bf16*  aoT = (bf16*)p_aoT;
    float* s   = (float*)p_s;
    bf16*  att = (bf16*)p_att;
    bf16*  wb  = (bf16*)p_wb;

    // 0) bf16 weights + GroupNorm + hnT
    prep_kernel<<<256, 256>>>(wq, wk, wv, wo, wb);
    groupnorm_kernel<<<NB * 32, 256>>>(x, gns, gnb, hn);
    transpose_bf16_kernel<<<dim3(NTOK / 32, NCH / 32, NB), 256>>>(hn, hnT);

    // 1) qT[tok][ch] = hnT . wq^T + bq (per-col); kT likewise
    hgemm<1, 2, 0><<<dim3(2, 32, NB), 256>>>(
        hnT, wb, qT, bq, nullptr, 1.f, 1.f,
        NTOK, NCH, NCH, CHB, 0, CHB);
    hgemm<1, 2, 0><<<dim3(2, 32, NB), 256>>>(
        hnT, wb + 65536, kT, bk, nullptr, 1.f, 1.f,
        NTOK, NCH, NCH, CHB, 0, CHB);
    // v[ch][tok] = wv . hnT^T + bv (per-row)
    hgemm<1, 1, 0><<<dim3(32, 2, NB), 256>>>(
        wb + 131072, hnT, v, bv, nullptr, 1.f, 1.f,
        NCH, NTOK, NCH, 0, CHB, CHB);

    // 2) logits s[q][k] = (1/16) qT . kT^T   (fp32 out)
    hgemm<0, 0, 0><<<dim3(32, 32, NB), 256>>>(
        qT, kT, s, nullptr, nullptr, 0.0625f, 1.f,
        NTOK, NTOK, NCH, CHB, CHB, NNB);

    // 3) softmax rows -> bf16 att
    softmax_bf16_kernel<<<NB * NTOK, 256>>>(s, att);

    // 4) aoT[q][ch] = att . v^T
    hgemm<1, 0, 0><<<dim3(2, 32, NB), 256>>>(
        att, v, aoT, nullptr, nullptr, 1.f, 1.f,
        NTOK, NCH, NTOK, NNB, CHB, CHB);

    // 5) out[ch][tok] = (wo . aoT^T + bo + x) / sqrt(2)
    hgemm<0, 1, 1><<<dim3(32, 2, NB), 256>>>(
        wb + 196608, aoT, out, bo, x, 1.f, 0.70710678118654752f,
        NCH, NTOK, NCH, 0, CHB, CHB);
}

// round 9
// speedup vs baseline: 49.5036x; 1.0545x over previous
#include <cuda_runtime.h>
#include <cuda_bf16.h>
#include <cuda_fp16.h>
#include <cstdint>
#include <cstddef>

// Problem constants
#define NB    8
#define NCH   256
#define NTOK  4096
#define CHB   ((size_t)NCH * NTOK)
#define NNB   ((size_t)NTOK * NTOK)

typedef __nv_bfloat16 bf16;

// Static scratch — accessed ONLY via cudaGetSymbolAddress-resolved pointers.
__device__ __align__(256) float  g_hn [NB * CHB];   // groupnorm out fp32 [ch][tok]
__device__ __align__(256) bf16   g_hnT[NB * CHB];   // [tok][ch]
__device__ __align__(256) bf16   g_qT [NB * CHB];   // [tok][ch]
__device__ __align__(256) bf16   g_kT [NB * CHB];   // [tok][ch]
__device__ __align__(256) bf16   g_v  [NB * CHB];   // [ch][tok]
__device__ __align__(256) bf16   g_aoT[NB * CHB];   // [tok][ch]
__device__ __align__(256) __half g_s  [NB * NNB];   // logits fp16
__device__ __align__(256) bf16   g_att[NB * NNB];   // probs bf16
__device__ __align__(256) bf16   g_wb [4 * NCH * NCH]; // bf16 weights q,k,v,o

// ---------------------------------------------------------------------------
// prep: weights fp32 -> bf16
// ---------------------------------------------------------------------------
__global__ __launch_bounds__(256) void prep_kernel(
    const float* __restrict__ wq, const float* __restrict__ wk,
    const float* __restrict__ wv, const float* __restrict__ wo,
    bf16* __restrict__ wb)
{
    int i = blockIdx.x * 256 + threadIdx.x;  // 65536
    wb[i]          = __float2bfloat16(wq[i]);
    wb[ 65536 + i] = __float2bfloat16(wk[i]);
    wb[131072 + i] = __float2bfloat16(wv[i]);
    wb[196608 + i] = __float2bfloat16(wo[i]);
}

// ---------------------------------------------------------------------------
// GroupNorm (proven, fp32 out)
// ---------------------------------------------------------------------------
__global__ __launch_bounds__(256) void groupnorm_kernel(
    const float* __restrict__ x, const float* __restrict__ sc,
    const float* __restrict__ bi, float* __restrict__ out)
{
    int b = blockIdx.x >> 5;
    int g = blockIdx.x & 31;
    size_t base = ((size_t)b * NCH + (size_t)g * 8) * NTOK;
    const float4* px = (const float4*)(x + base);
    float4* po = (float4*)(out + base);
    int t = threadIdx.x;

    float s = 0.f, ss = 0.f;
#pragma unroll
    for (int r = 0; r < 32; r++) {
        float4 f = px[r * 256 + t];
        s  += f.x + f.y + f.z + f.w;
        ss += f.x * f.x + f.y * f.y + f.z * f.z + f.w * f.w;
    }
#pragma unroll
    for (int o = 16; o; o >>= 1) {
        s  += __shfl_xor_sync(0xffffffffu, s, o);
        ss += __shfl_xor_sync(0xffffffffu, ss, o);
    }
    __shared__ float rs[8], rss[8];
    __shared__ float s_mean, s_rstd;
    if ((t & 31) == 0) { rs[t >> 5] = s; rss[t >> 5] = ss; }
    __syncthreads();
    if (t == 0) {
        float S = 0.f, SS = 0.f;
#pragma unroll
        for (int i = 0; i < 8; i++) { S += rs[i]; SS += rss[i]; }
        float m = S * (1.f / 32768.f);
        float var = SS * (1.f / 32768.f) - m * m;
        s_mean = m;
        s_rstd = rsqrtf(var + 1e-6f);
    }
    __syncthreads();
    float m = s_mean, rstd = s_rstd;
#pragma unroll
    for (int r = 0; r < 32; r++) {
        int idx = r * 256 + t;
        int c = g * 8 + (idx >> 10);
        float a = sc[c] * rstd;
        float bb = bi[c] - m * a;
        float4 f = px[idx];
        po[idx] = make_float4(f.x * a + bb, f.y * a + bb, f.z * a + bb, f.w * a + bb);
    }
}

// ---------------------------------------------------------------------------
// Transpose hn [256][4096] fp32 -> hnT [4096][256] bf16
// ---------------------------------------------------------------------------
__global__ __launch_bounds__(256) void transpose_bf16_kernel(
    const float* __restrict__ in, bf16* __restrict__ out)
{
    __shared__ float tile[32][33];
    size_t z = blockIdx.z;
    const float* ip = in + z * CHB;
    bf16* op = out + z * CHB;
    int n0 = blockIdx.x * 32, c0 = blockIdx.y * 32;
    int tx = threadIdx.x & 31, ty = threadIdx.x >> 5;
#pragma unroll
    for (int j = 0; j < 32; j += 8)
        tile[ty + j][tx] = ip[(size_t)(c0 + ty + j) * NTOK + n0 + tx];
    __syncthreads();
#pragma unroll
    for (int j = 0; j < 32; j += 8)
        op[(size_t)(n0 + ty + j) * NCH + c0 + tx] = __float2bfloat16(tile[tx][ty + j]);
}

// ---------------------------------------------------------------------------
// Warp-MMA bf16 GEMM, 3-stage cp.async pipeline (single barrier per chunk).
// C[m][n] = alpha * sum_k A[m][k]*B[n][k] (+bias)(+resid)*outscale
// A: [M][K] bf16 row-major, B: [N][K] bf16 row-major.
// Tile 128x128, 8 warps (2x4), warp tile 64x32, K-chunk 32.
// OUT_MODE: 0 fp32, 1 bf16, 2 fp16.  BIAS_MODE: 0 none, 1 bias[m], 2 bias[n].
// ---------------------------------------------------------------------------
#define ASTRB 40                 // bf16 row stride (80B) -> ldmatrix conflict-free
#define OPB   (128 * ASTRB * 2)  // 10240 B per operand tile
#define BUFB  (2 * OPB)          // 20480 B per pipeline stage (A + B)
#define SMEM_DYN (3 * BUFB)      // 61440 B

__device__ __forceinline__ void mma16816(float* c, unsigned a0, unsigned a1,
                                         unsigned a2, unsigned a3,
                                         unsigned b0, unsigned b1)
{
    asm volatile(
        "mma.sync.aligned.m16n8k16.row.col.f32.bf16.bf16.f32 "
        "{%0,%1,%2,%3},{%4,%5,%6,%7},{%8,%9},{%0,%1,%2,%3};"
        : "+f"(c[0]), "+f"(c[1]), "+f"(c[2]), "+f"(c[3])
        : "r"(a0), "r"(a1), "r"(a2), "r"(a3), "r"(b0), "r"(b1));
}

#define LDSM4(r0, r1, r2, r3, addr) \
    asm volatile("ldmatrix.sync.aligned.m8n8.x4.shared.b16 {%0,%1,%2,%3}, [%4];" \
                 : "=r"(r0), "=r"(r1), "=r"(r2), "=r"(r3) : "r"(addr))

#define CP16(dst, src) \
    asm volatile("cp.async.cg.shared.global [%0], [%1], 16;" :: "r"(dst), "l"(src))

template<int OUT_MODE, int BIAS_MODE, int RESID>
__global__ __launch_bounds__(256, 2) void hgemm(
    const bf16* __restrict__ A, const bf16* __restrict__ B,
    void* __restrict__ Cout, const float* __restrict__ bias,
    const float* __restrict__ resid, float alpha, float outscale,
    int M, int N, int K, size_t bA, size_t bB, size_t bC)
{
    extern __shared__ char dynsm[];
    uint32_t sBase = (uint32_t)__cvta_generic_to_shared(dynsm);

    int t = threadIdx.x;
    int m0 = blockIdx.y * 128, n0 = blockIdx.x * 128;
    size_t z = blockIdx.z;

    int wid = t >> 5, lane = t & 31;
    int mw = (wid & 1) * 64, nw = (wid >> 1) * 32;
    int lr = lane >> 2, lc = lane & 3;

    float acc[64];
#pragma unroll
    for (int i = 0; i < 64; i++) acc[i] = 0.f;

    // cp.async staging map: thread t -> rows (t>>2) and (t>>2)+64, 16B granule t&3
    int rowa = t >> 2, gcol = t & 3;
    const bf16* Ab = A + z * bA + (size_t)(m0 + rowa) * K + gcol * 8;
    const bf16* Bb = B + z * bB + (size_t)(n0 + rowa) * K + gcol * 8;
    size_t rstep = (size_t)64 * K;

    uint32_t stOff   = (uint32_t)(rowa * ASTRB + gcol * 8) * 2;
    uint32_t stOff64 = stOff + (uint32_t)(64 * ASTRB) * 2;

    // ldmatrix lane maps
    int arow_l = (lane & 7) + ((lane >> 3) & 1) * 8;  // A: 0..15
    int akof_l = (lane >> 4) * 8;                     //    k 0 or 8
    int brow_l = (lane & 7) + ((lane >> 4) & 1) * 8;  // B
    int bkof_l = ((lane >> 3) & 1) * 8;

    int nkt = K / 32;

#define STAGE(chunk, buf) do {                                        \
        size_t go = (size_t)(chunk) * 32;                             \
        uint32_t ab = sBase + (uint32_t)(buf) * BUFB;                 \
        uint32_t bb2 = ab + OPB;                                      \
        CP16(ab + stOff,    Ab + go);                                 \
        CP16(ab + stOff64,  Ab + go + rstep);                         \
        CP16(bb2 + stOff,   Bb + go);                                 \
        CP16(bb2 + stOff64, Bb + go + rstep);                         \
        asm volatile("cp.async.commit_group;" ::: "memory");          \
    } while (0)

    // prologue: stage chunks 0 and 1
    STAGE(0, 0);
    STAGE(1, 1);

    int buf = 0;
    for (int kt = 0; kt < nkt; kt++) {
        if (kt + 1 < nkt) {
            asm volatile("cp.async.wait_group 1;" ::: "memory");
        } else {
            asm volatile("cp.async.wait_group 0;" ::: "memory");
        }
        __syncthreads();   // single barrier: data visible + prev compute retired

        if (kt + 2 < nkt) {
            int nb = buf + 2; if (nb >= 3) nb -= 3;
            STAGE(kt + 2, nb);
        }

        uint32_t aBuf = sBase + (uint32_t)buf * BUFB;
        uint32_t bBuf = aBuf + OPB;
#pragma unroll
        for (int ks = 0; ks < 2; ks++) {
            int ko = ks * 16;
            unsigned bfr[4][2];
#pragma unroll
            for (int np = 0; np < 2; np++) {
                uint32_t ba = bBuf + (uint32_t)((nw + np * 16 + brow_l) * ASTRB
                                                + ko + bkof_l) * 2;
                LDSM4(bfr[np * 2][0], bfr[np * 2][1],
                      bfr[np * 2 + 1][0], bfr[np * 2 + 1][1], ba);
            }
#pragma unroll
            for (int mf = 0; mf < 4; mf++) {
                unsigned a0, a1, a2, a3;
                uint32_t aa = aBuf + (uint32_t)((mw + mf * 16 + arow_l) * ASTRB
                                                + ko + akof_l) * 2;
                LDSM4(a0, a1, a2, a3, aa);
#pragma unroll
                for (int nf = 0; nf < 4; nf++)
                    mma16816(acc + (mf * 4 + nf) * 4, a0, a1, a2, a3,
                             bfr[nf][0], bfr[nf][1]);
            }
        }
        if (++buf == 3) buf = 0;
    }
#undef STAGE

    // epilogue
#pragma unroll
    for (int mf = 0; mf < 4; mf++) {
#pragma unroll
        for (int nf = 0; nf < 4; nf++) {
            float* c = acc + (mf * 4 + nf) * 4;
            int mg = m0 + mw + mf * 16 + lr;
            int ng = n0 + nw + nf * 8 + 2 * lc;
            float o0 = c[0] * alpha, o1 = c[1] * alpha;
            float o2 = c[2] * alpha, o3 = c[3] * alpha;
            if (BIAS_MODE == 1) {
                float b0 = bias[mg], b1 = bias[mg + 8];
                o0 += b0; o1 += b0; o2 += b1; o3 += b1;
            } else if (BIAS_MODE == 2) {
                float b0 = bias[ng], b1 = bias[ng + 1];
                o0 += b0; o1 += b1; o2 += b0; o3 += b1;
            }
            size_t i0 = (size_t)mg * N + ng;
            size_t i1 = (size_t)(mg + 8) * N + ng;
            if (RESID) {
                const float* Rb = resid + z * bC;
                o0 = (o0 + Rb[i0])     * outscale;
                o1 = (o1 + Rb[i0 + 1]) * outscale;
                o2 = (o2 + Rb[i1])     * outscale;
                o3 = (o3 + Rb[i1 + 1]) * outscale;
            }
            if (OUT_MODE == 1) {
                bf16* Cb = (bf16*)Cout + z * bC;
                __nv_bfloat162 h0 = __floats2bfloat162_rn(o0, o1);
                __nv_bfloat162 h1 = __floats2bfloat162_rn(o2, o3);
                *(uint32_t*)&Cb[i0] = *(uint32_t*)&h0;
                *(uint32_t*)&Cb[i1] = *(uint32_t*)&h1;
            } else if (OUT_MODE == 2) {
                __half* Cb = (__half*)Cout + z * bC;
                __half2 h0 = __floats2half2_rn(o0, o1);
                __half2 h1 = __floats2half2_rn(o2, o3);
                *(uint32_t*)&Cb[i0] = *(uint32_t*)&h0;
                *(uint32_t*)&Cb[i1] = *(uint32_t*)&h1;
            } else {
                float* Cb = (float*)Cout + z * bC;
                float2 p0 = {o0, o1}, p1 = {o2, o3};
                *(float2*)&Cb[i0] = p0;
                *(float2*)&Cb[i1] = p1;
            }
        }
    }
}

// ---------------------------------------------------------------------------
// Softmax rows (fp16 in, bf16 out), polynomial exp on the FFMA pipe.
// ---------------------------------------------------------------------------
__device__ __forceinline__ float fexp(float x) {  // x <= 0
    float zc = fmaxf(x * 1.4426950408889634f, -126.0f);
    float r = zc + 12582912.0f;
    float zi = r - 12582912.0f;
    float f = zc - zi;
    int e = (__float_as_int(r) & 0x7FFFFF) - 0x400000;
    float p = 1.3333558e-3f;
    p = fmaf(p, f, 9.6181291e-3f);
    p = fmaf(p, f, 5.5504109e-2f);
    p = fmaf(p, f, 2.4022651e-1f);
    p = fmaf(p, f, 6.9314718e-1f);
    p = fmaf(p, f, 1.0f);
    return __int_as_float((e + 127) << 23) * p;
}

__global__ __launch_bounds__(256) void softmax_bf16_kernel(
    const __half* __restrict__ s, bf16* __restrict__ att)
{
    size_t row = blockIdx.x;
    const uint2* p = (const uint2*)(s + row * (size_t)NTOK);
    uint2* q = (uint2*)(att + row * (size_t)NTOK);
    int t = threadIdx.x;

    float v[4][4];
    float mx = -3.0e38f;
#pragma unroll
    for (int r = 0; r < 4; r++) {
        uint2 u = p[r * 256 + t];
        __half2 h0 = *(__half2*)&u.x;
        __half2 h1 = *(__half2*)&u.y;
        float2 f0 = __half22float2(h0);
        float2 f1 = __half22float2(h1);
        v[r][0] = f0.x; v[r][1] = f0.y; v[r][2] = f1.x; v[r][3] = f1.y;
        mx = fmaxf(mx, fmaxf(fmaxf(v[r][0], v[r][1]), fmaxf(v[r][2], v[r][3])));
    }
#pragma unroll
    for (int o = 16; o; o >>= 1) mx = fmaxf(mx, __shfl_xor_sync(0xffffffffu, mx, o));
    __shared__ float red[8];
    if ((t & 31) == 0) red[t >> 5] = mx;
    __syncthreads();
#pragma unroll
    for (int i = 0; i < 8; i++) mx = fmaxf(mx, red[i]);
    __syncthreads();

    float sum = 0.f;
#pragma unroll
    for (int r = 0; r < 4; r++) {
#pragma unroll
        for (int j = 0; j < 4; j++) {
            v[r][j] = fexp(v[r][j] - mx);
            sum += v[r][j];
        }
    }
#pragma unroll
    for (int o = 16; o; o >>= 1) sum += __shfl_xor_sync(0xffffffffu, sum, o);
    if ((t & 31) == 0) red[t >> 5] = sum;
    __syncthreads();
    float tot = 0.f;
#pragma unroll
    for (int i = 0; i < 8; i++) tot += red[i];
    float inv = 1.f / tot;
#pragma unroll
    for (int r = 0; r < 4; r++) {
        __nv_bfloat162 h0 = __floats2bfloat162_rn(v[r][0] * inv, v[r][1] * inv);
        __nv_bfloat162 h1 = __floats2bfloat162_rn(v[r][2] * inv, v[r][3] * inv);
        uint2 u;
        u.x = *(uint32_t*)&h0;
        u.y = *(uint32_t*)&h1;
        q[r * 256 + t] = u;
    }
}

// ---------------------------------------------------------------------------
// kernel_launch — scratch via cudaGetSymbolAddress (true device addresses).
// ---------------------------------------------------------------------------
extern "C" void kernel_launch(void* const* d_in, const int* in_sizes, int n_in,
                              void* d_out, int out_size)
{
    const float* x   = (const float*)d_in[0];
    const float* gns = (const float*)d_in[1];
    const float* gnb = (const float*)d_in[2];
    const float* wq  = (const float*)d_in[3];
    const float* bq  = (const float*)d_in[4];
    const float* wk  = (const float*)d_in[5];
    const float* bk  = (const float*)d_in[6];
    const float* wv  = (const float*)d_in[7];
    const float* bv  = (const float*)d_in[8];
    const float* wo  = (const float*)d_in[9];
    const float* bo  = (const float*)d_in[10];
    float* out = (float*)d_out;

    void *p_hn, *p_hnT, *p_qT, *p_kT, *p_v, *p_aoT, *p_s, *p_att, *p_wb;
    cudaGetSymbolAddress(&p_hn,  g_hn);
    cudaGetSymbolAddress(&p_hnT, g_hnT);
    cudaGetSymbolAddress(&p_qT,  g_qT);
    cudaGetSymbolAddress(&p_kT,  g_kT);
    cudaGetSymbolAddress(&p_v,   g_v);
    cudaGetSymbolAddress(&p_aoT, g_aoT);
    cudaGetSymbolAddress(&p_s,   g_s);
    cudaGetSymbolAddress(&p_att, g_att);
    cudaGetSymbolAddress(&p_wb,  g_wb);
    float*  hn  = (float*)p_hn;
    bf16*   hnT = (bf16*)p_hnT;
    bf16*   qT  = (bf16*)p_qT;
    bf16*   kT  = (bf16*)p_kT;
    bf16*   v   = (bf16*)p_v;
    bf16*   aoT = (bf16*)p_aoT;
    __half* s   = (__half*)p_s;
    bf16*   att = (bf16*)p_att;
    bf16*   wb  = (bf16*)p_wb;

    // opt-in dynamic smem (61440 B/CTA; 2 CTAs/SM = 120 KB of 228 KB)
    cudaFuncSetAttribute(hgemm<1, 2, 0>, cudaFuncAttributeMaxDynamicSharedMemorySize, SMEM_DYN);
    cudaFuncSetAttribute(hgemm<1, 1, 0>, cudaFuncAttributeMaxDynamicSharedMemorySize, SMEM_DYN);
    cudaFuncSetAttribute(hgemm<2, 0, 0>, cudaFuncAttributeMaxDynamicSharedMemorySize, SMEM_DYN);
    cudaFuncSetAttribute(hgemm<1, 0, 0>, cudaFuncAttributeMaxDynamicSharedMemorySize, SMEM_DYN);
    cudaFuncSetAttribute(hgemm<0, 1, 1>, cudaFuncAttributeMaxDynamicSharedMemorySize, SMEM_DYN);

    // 0) bf16 weights + GroupNorm + hnT
    prep_kernel<<<256, 256>>>(wq, wk, wv, wo, wb);
    groupnorm_kernel<<<NB * 32, 256>>>(x, gns, gnb, hn);
    transpose_bf16_kernel<<<dim3(NTOK / 32, NCH / 32, NB), 256>>>(hn, hnT);

    // 1) qT[tok][ch] = hnT . wq^T + bq (per-col); kT likewise
    hgemm<1, 2, 0><<<dim3(2, 32, NB), 256, SMEM_DYN>>>(
        hnT, wb, qT, bq, nullptr, 1.f, 1.f,
        NTOK, NCH, NCH, CHB, 0, CHB);
    hgemm<1, 2, 0><<<dim3(2, 32, NB), 256, SMEM_DYN>>>(
        hnT, wb + 65536, kT, bk, nullptr, 1.f, 1.f,
        NTOK, NCH, NCH, CHB, 0, CHB);
    // v[ch][tok] = wv . hnT^T + bv (per-row)
    hgemm<1, 1, 0><<<dim3(32, 2, NB), 256, SMEM_DYN>>>(
        wb + 131072, hnT, v, bv, nullptr, 1.f, 1.f,
        NCH, NTOK, NCH, 0, CHB, CHB);

    // 2) logits s[q][k] = (1/16) qT . kT^T   (fp16 out)
    hgemm<2, 0, 0><<<dim3(32, 32, NB), 256, SMEM_DYN>>>(
        qT, kT, s, nullptr, nullptr, 0.0625f, 1.f,
        NTOK, NTOK, NCH, CHB, CHB, NNB);

    // 3) softmax rows (fp16 in) -> bf16 att
    softmax_bf16_kernel<<<NB * NTOK, 256>>>(s, att);

    // 4) aoT[q][ch] = att . v^T
    hgemm<1, 0, 0><<<dim3(2, 32, NB), 256, SMEM_DYN>>>(
        att, v, aoT, nullptr, nullptr, 1.f, 1.f,
        NTOK, NCH, NTOK, NNB, CHB, CHB);

    // 5) out[ch][tok] = (wo . aoT^T + bo + x) / sqrt(2)
    hgemm<0, 1, 1><<<dim3(32, 2, NB), 256, SMEM_DYN>>>(
        wb + 196608, aoT, out, bo, x, 1.f, 0.70710678118654752f,
        NCH, NTOK, NCH, 0, CHB, CHB);
}

// round 10
// speedup vs baseline: 51.4027x; 1.0384x over previous
#include <cuda_runtime.h>
#include <cuda_bf16.h>
#include <cstdint>
#include <cstddef>

// Problem constants
#define NB    8
#define NCH   256
#define NTOK  4096
#define CHB   ((size_t)NCH * NTOK)

typedef __nv_bfloat16 bf16;

// Static scratch — accessed ONLY via cudaGetSymbolAddress-resolved pointers.
__device__ __align__(256) float  g_hn [NB * CHB];   // groupnorm out fp32 [ch][tok]
__device__ __align__(256) bf16   g_hnT[NB * CHB];   // [tok][ch]
__device__ __align__(256) bf16   g_qT [NB * CHB];   // [tok][ch]
__device__ __align__(256) bf16   g_kT [NB * CHB];   // [tok][ch]
__device__ __align__(256) bf16   g_v  [NB * CHB];   // [ch][tok]
__device__ __align__(256) bf16   g_aoT[NB * CHB];   // [tok][ch]
__device__ __align__(256) bf16   g_wb [4 * NCH * NCH]; // bf16 weights q,k,v,o

// ---------------------------------------------------------------------------
// common PTX helpers
// ---------------------------------------------------------------------------
__device__ __forceinline__ void mma16816(float* c, unsigned a0, unsigned a1,
                                         unsigned a2, unsigned a3,
                                         unsigned b0, unsigned b1)
{
    asm volatile(
        "mma.sync.aligned.m16n8k16.row.col.f32.bf16.bf16.f32 "
        "{%0,%1,%2,%3},{%4,%5,%6,%7},{%8,%9},{%0,%1,%2,%3};"
        : "+f"(c[0]), "+f"(c[1]), "+f"(c[2]), "+f"(c[3])
        : "r"(a0), "r"(a1), "r"(a2), "r"(a3), "r"(b0), "r"(b1));
}

#define LDSM4(r0, r1, r2, r3, addr) \
    asm volatile("ldmatrix.sync.aligned.m8n8.x4.shared.b16 {%0,%1,%2,%3}, [%4];" \
                 : "=r"(r0), "=r"(r1), "=r"(r2), "=r"(r3) : "r"(addr))

#define CP16(dst, src) \
    asm volatile("cp.async.cg.shared.global [%0], [%1], 16;" :: "r"(dst), "l"(src))
#define CPCOMMIT() asm volatile("cp.async.commit_group;" ::: "memory")
#define CPWAIT1()  asm volatile("cp.async.wait_group 1;" ::: "memory")
#define CPWAIT0()  asm volatile("cp.async.wait_group 0;" ::: "memory")

__device__ __forceinline__ unsigned pkbf(float x, float y) {
    __nv_bfloat162 h = __floats2bfloat162_rn(x, y);
    return *(unsigned*)&h;
}

// ---------------------------------------------------------------------------
// prep: weights fp32 -> bf16
// ---------------------------------------------------------------------------
__global__ __launch_bounds__(256) void prep_kernel(
    const float* __restrict__ wq, const float* __restrict__ wk,
    const float* __restrict__ wv, const float* __restrict__ wo,
    bf16* __restrict__ wb)
{
    int i = blockIdx.x * 256 + threadIdx.x;  // 65536
    wb[i]          = __float2bfloat16(wq[i]);
    wb[ 65536 + i] = __float2bfloat16(wk[i]);
    wb[131072 + i] = __float2bfloat16(wv[i]);
    wb[196608 + i] = __float2bfloat16(wo[i]);
}

// ---------------------------------------------------------------------------
// GroupNorm (proven, fp32 out)
// ---------------------------------------------------------------------------
__global__ __launch_bounds__(256) void groupnorm_kernel(
    const float* __restrict__ x, const float* __restrict__ sc,
    const float* __restrict__ bi, float* __restrict__ out)
{
    int b = blockIdx.x >> 5;
    int g = blockIdx.x & 31;
    size_t base = ((size_t)b * NCH + (size_t)g * 8) * NTOK;
    const float4* px = (const float4*)(x + base);
    float4* po = (float4*)(out + base);
    int t = threadIdx.x;

    float s = 0.f, ss = 0.f;
#pragma unroll
    for (int r = 0; r < 32; r++) {
        float4 f = px[r * 256 + t];
        s  += f.x + f.y + f.z + f.w;
        ss += f.x * f.x + f.y * f.y + f.z * f.z + f.w * f.w;
    }
#pragma unroll
    for (int o = 16; o; o >>= 1) {
        s  += __shfl_xor_sync(0xffffffffu, s, o);
        ss += __shfl_xor_sync(0xffffffffu, ss, o);
    }
    __shared__ float rs[8], rss[8];
    __shared__ float s_mean, s_rstd;
    if ((t & 31) == 0) { rs[t >> 5] = s; rss[t >> 5] = ss; }
    __syncthreads();
    if (t == 0) {
        float S = 0.f, SS = 0.f;
#pragma unroll
        for (int i = 0; i < 8; i++) { S += rs[i]; SS += rss[i]; }
        float m = S * (1.f / 32768.f);
        float var = SS * (1.f / 32768.f) - m * m;
        s_mean = m;
        s_rstd = rsqrtf(var + 1e-6f);
    }
    __syncthreads();
    float m = s_mean, rstd = s_rstd;
#pragma unroll
    for (int r = 0; r < 32; r++) {
        int idx = r * 256 + t;
        int c = g * 8 + (idx >> 10);
        float a = sc[c] * rstd;
        float bb = bi[c] - m * a;
        float4 f = px[idx];
        po[idx] = make_float4(f.x * a + bb, f.y * a + bb, f.z * a + bb, f.w * a + bb);
    }
}

// ---------------------------------------------------------------------------
// Transpose hn [256][4096] fp32 -> hnT [4096][256] bf16
// ---------------------------------------------------------------------------
__global__ __launch_bounds__(256) void transpose_bf16_kernel(
    const float* __restrict__ in, bf16* __restrict__ out)
{
    __shared__ float tile[32][33];
    size_t z = blockIdx.z;
    const float* ip = in + z * CHB;
    bf16* op = out + z * CHB;
    int n0 = blockIdx.x * 32, c0 = blockIdx.y * 32;
    int tx = threadIdx.x & 31, ty = threadIdx.x >> 5;
#pragma unroll
    for (int j = 0; j < 32; j += 8)
        tile[ty + j][tx] = ip[(size_t)(c0 + ty + j) * NTOK + n0 + tx];
    __syncthreads();
#pragma unroll
    for (int j = 0; j < 32; j += 8)
        op[(size_t)(n0 + ty + j) * NCH + c0 + tx] = __float2bfloat16(tile[tx][ty + j]);
}

// ---------------------------------------------------------------------------
// hgemm: warp-MMA bf16 GEMM, 3-stage cp.async pipeline (round-9 proven).
// Used for q/k/v projections and the final projection.
// ---------------------------------------------------------------------------
#define ASTRB 40
#define OPB   (128 * ASTRB * 2)
#define BUFB  (2 * OPB)
#define SMEM_DYN (3 * BUFB)

template<int OUT_MODE, int BIAS_MODE, int RESID>   // OUT_MODE: 0 fp32, 1 bf16
__global__ __launch_bounds__(256, 2) void hgemm(
    const bf16* __restrict__ A, const bf16* __restrict__ B,
    void* __restrict__ Cout, const float* __restrict__ bias,
    const float* __restrict__ resid, float alpha, float outscale,
    int M, int N, int K, size_t bA, size_t bB, size_t bC)
{
    extern __shared__ char dynsm[];
    uint32_t sBase = (uint32_t)__cvta_generic_to_shared(dynsm);

    int t = threadIdx.x;
    int m0 = blockIdx.y * 128, n0 = blockIdx.x * 128;
    size_t z = blockIdx.z;

    int wid = t >> 5, lane = t & 31;
    int mw = (wid & 1) * 64, nw = (wid >> 1) * 32;
    int lr = lane >> 2, lc = lane & 3;

    float acc[64];
#pragma unroll
    for (int i = 0; i < 64; i++) acc[i] = 0.f;

    int rowa = t >> 2, gcol = t & 3;
    const bf16* Ab = A + z * bA + (size_t)(m0 + rowa) * K + gcol * 8;
    const bf16* Bb = B + z * bB + (size_t)(n0 + rowa) * K + gcol * 8;
    size_t rstep = (size_t)64 * K;

    uint32_t stOff   = (uint32_t)(rowa * ASTRB + gcol * 8) * 2;
    uint32_t stOff64 = stOff + (uint32_t)(64 * ASTRB) * 2;

    int arow_l = (lane & 7) + ((lane >> 3) & 1) * 8;
    int akof_l = (lane >> 4) * 8;
    int brow_l = (lane & 7) + ((lane >> 4) & 1) * 8;
    int bkof_l = ((lane >> 3) & 1) * 8;

    int nkt = K / 32;

#define STAGE(chunk, buf) do {                                        \
        size_t go = (size_t)(chunk) * 32;                             \
        uint32_t ab = sBase + (uint32_t)(buf) * BUFB;                 \
        uint32_t bb2 = ab + OPB;                                      \
        CP16(ab + stOff,    Ab + go);                                 \
        CP16(ab + stOff64,  Ab + go + rstep);                         \
        CP16(bb2 + stOff,   Bb + go);                                 \
        CP16(bb2 + stOff64, Bb + go + rstep);                         \
        CPCOMMIT();                                                   \
    } while (0)

    STAGE(0, 0);
    STAGE(1, 1);

    int buf = 0;
    for (int kt = 0; kt < nkt; kt++) {
        if (kt + 1 < nkt) CPWAIT1(); else CPWAIT0();
        __syncthreads();

        if (kt + 2 < nkt) {
            int nb = buf + 2; if (nb >= 3) nb -= 3;
            STAGE(kt + 2, nb);
        }

        uint32_t aBuf = sBase + (uint32_t)buf * BUFB;
        uint32_t bBuf = aBuf + OPB;
#pragma unroll
        for (int ks = 0; ks < 2; ks++) {
            int ko = ks * 16;
            unsigned bfr[4][2];
#pragma unroll
            for (int np = 0; np < 2; np++) {
                uint32_t ba = bBuf + (uint32_t)((nw + np * 16 + brow_l) * ASTRB
                                                + ko + bkof_l) * 2;
                LDSM4(bfr[np * 2][0], bfr[np * 2][1],
                      bfr[np * 2 + 1][0], bfr[np * 2 + 1][1], ba);
            }
#pragma unroll
            for (int mf = 0; mf < 4; mf++) {
                unsigned a0, a1, a2, a3;
                uint32_t aa = aBuf + (uint32_t)((mw + mf * 16 + arow_l) * ASTRB
                                                + ko + akof_l) * 2;
                LDSM4(a0, a1, a2, a3, aa);
#pragma unroll
                for (int nf = 0; nf < 4; nf++)
                    mma16816(acc + (mf * 4 + nf) * 4, a0, a1, a2, a3,
                             bfr[nf][0], bfr[nf][1]);
            }
        }
        if (++buf == 3) buf = 0;
    }
#undef STAGE

#pragma unroll
    for (int mf = 0; mf < 4; mf++) {
#pragma unroll
        for (int nf = 0; nf < 4; nf++) {
            float* c = acc + (mf * 4 + nf) * 4;
            int mg = m0 + mw + mf * 16 + lr;
            int ng = n0 + nw + nf * 8 + 2 * lc;
            float o0 = c[0] * alpha, o1 = c[1] * alpha;
            float o2 = c[2] * alpha, o3 = c[3] * alpha;
            if (BIAS_MODE == 1) {
                float b0 = bias[mg], b1 = bias[mg + 8];
                o0 += b0; o1 += b0; o2 += b1; o3 += b1;
            } else if (BIAS_MODE == 2) {
                float b0 = bias[ng], b1 = bias[ng + 1];
                o0 += b0; o1 += b1; o2 += b0; o3 += b1;
            }
            size_t i0 = (size_t)mg * N + ng;
            size_t i1 = (size_t)(mg + 8) * N + ng;
            if (RESID) {
                const float* Rb = resid + z * bC;
                o0 = (o0 + Rb[i0])     * outscale;
                o1 = (o1 + Rb[i0 + 1]) * outscale;
                o2 = (o2 + Rb[i1])     * outscale;
                o3 = (o3 + Rb[i1 + 1]) * outscale;
            }
            if (OUT_MODE == 1) {
                bf16* Cb = (bf16*)Cout + z * bC;
                *(uint32_t*)&Cb[i0] = pkbf(o0, o1);
                *(uint32_t*)&Cb[i1] = pkbf(o2, o3);
            } else {
                float* Cb = (float*)Cout + z * bC;
                float2 p0 = {o0, o1}, p1 = {o2, o3};
                *(float2*)&Cb[i0] = p0;
                *(float2*)&Cb[i1] = p1;
            }
        }
    }
}

// ---------------------------------------------------------------------------
// Fused flash attention: logits + online softmax + att@V in one kernel.
// Grid (32 q-tiles, 8 batches), 256 threads. Each warp owns 16 q-rows x full
// tile. q tile resident in smem; kT and v streamed in 32-wide chunks through
// a 3-deep cp.async ring. S stays in registers; its C-fragments convert
// register-exactly into A-fragments for P@V (FA2 trick).
// ---------------------------------------------------------------------------
#define QSTR 264
#define CSTR 40
#define Q_BYTES (128 * QSTR * 2)      // 67584
#define CHUNK_BYTES 20480             // max(kT 128x40, v 256x40) * 2B
#define FSMEM (Q_BYTES + 3 * CHUNK_BYTES)  // 129024

__global__ __launch_bounds__(256, 1) void attn_fused(
    const bf16* __restrict__ qT, const bf16* __restrict__ kT,
    const bf16* __restrict__ vv, bf16* __restrict__ aoT)
{
    extern __shared__ char fsm[];
    const float alpha = 0.0625f;
    uint32_t sq = (uint32_t)__cvta_generic_to_shared(fsm);
    uint32_t sring = sq + Q_BYTES;

    int t = threadIdx.x, wid = t >> 5, lane = t & 31;
    int lr = lane >> 2, lc = lane & 3;
    size_t z = blockIdx.y;
    int q0 = blockIdx.x * 128;

    const bf16* qb = qT + z * CHB;
    const bf16* kb = kT + z * CHB;
    const bf16* vb = vv + z * CHB;

    int arow_l = (lane & 7) + ((lane >> 3) & 1) * 8;
    int akof_l = (lane >> 4) * 8;
    int brow_l = (lane & 7) + ((lane >> 4) & 1) * 8;
    int bkof_l = ((lane >> 3) & 1) * 8;

    // stage q tile (one commit group)
#pragma unroll
    for (int i = 0; i < 16; i++) {
        int idx = i * 256 + t;
        int row = idx >> 5, g = idx & 31;
        CP16(sq + (uint32_t)(row * QSTR + g * 8) * 2,
             qb + (size_t)(q0 + row) * NCH + g * 8);
    }
    CPCOMMIT();

    float out[32][4];
#pragma unroll
    for (int g = 0; g < 32; g++) {
        out[g][0] = 0.f; out[g][1] = 0.f; out[g][2] = 0.f; out[g][3] = 0.f;
    }
    float Sa[16][4];
    float m_a0 = -1e30f, m_a1 = -1e30f, l_a0 = 0.f, l_a1 = 0.f;

    // stage-ahead cursor
    int s_kti = 0, s_sub = 0, s_buf = 0;
#define FSTAGE() do {                                                       \
        uint32_t bs = sring + (uint32_t)s_buf * CHUNK_BYTES;                \
        if (s_sub < 8) {                                                    \
            const bf16* src = kb + (size_t)(s_kti * 128) * NCH + s_sub * 32;\
            _Pragma("unroll")                                               \
            for (int i = 0; i < 2; i++) {                                   \
                int idx = i * 256 + t; int row = idx >> 2, g = idx & 3;     \
                CP16(bs + (uint32_t)(row * CSTR + g * 8) * 2,               \
                     src + (size_t)row * NCH + g * 8);                      \
            }                                                               \
        } else {                                                            \
            const bf16* src = vb + s_kti * 128 + (s_sub - 8) * 32;          \
            _Pragma("unroll")                                               \
            for (int i = 0; i < 4; i++) {                                   \
                int idx = i * 256 + t; int row = idx >> 2, g = idx & 3;     \
                CP16(bs + (uint32_t)(row * CSTR + g * 8) * 2,               \
                     src + (size_t)row * NTOK + g * 8);                     \
            }                                                               \
        }                                                                   \
        CPCOMMIT();                                                         \
        if (++s_sub == 12) { s_sub = 0; s_kti++; }                          \
        if (++s_buf == 3) s_buf = 0;                                        \
    } while (0)

    FSTAGE();   // chunk 0
    FSTAGE();   // chunk 1

    int c_buf = 0;
    for (int kti = 0; kti < 32; kti++) {
        // ---- S = q . kT^T  (8 kT chunks of 32 ch) ----
#pragma unroll
        for (int sub = 0; sub < 8; sub++) {
            CPWAIT1();           // never the final chunk (final is a v chunk)
            __syncthreads();
            if (s_kti < 32) FSTAGE();
            uint32_t bs = sring + (uint32_t)c_buf * CHUNK_BYTES;
            if (++c_buf == 3) c_buf = 0;

            if (sub == 0) {
#pragma unroll
                for (int j = 0; j < 16; j++) {
                    Sa[j][0] = 0.f; Sa[j][1] = 0.f; Sa[j][2] = 0.f; Sa[j][3] = 0.f;
                }
            }
#pragma unroll
            for (int ks = 0; ks < 2; ks++) {
                unsigned a0, a1, a2, a3;
                LDSM4(a0, a1, a2, a3,
                      sq + (uint32_t)((wid * 16 + arow_l) * QSTR
                                      + sub * 32 + ks * 16 + akof_l) * 2);
#pragma unroll
                for (int ng = 0; ng < 8; ng++) {
                    unsigned b0, b1, b2, b3;
                    LDSM4(b0, b1, b2, b3,
                          bs + (uint32_t)((ng * 16 + brow_l) * CSTR
                                          + ks * 16 + bkof_l) * 2);
                    mma16816(Sa[2 * ng],     a0, a1, a2, a3, b0, b1);
                    mma16816(Sa[2 * ng + 1], a0, a1, a2, a3, b2, b3);
                }
            }
        }

        // ---- online softmax update (quad shuffles only) ----
        {
            float mx0 = -1e30f, mx1 = -1e30f;
#pragma unroll
            for (int j = 0; j < 16; j++) {
                mx0 = fmaxf(mx0, fmaxf(Sa[j][0], Sa[j][1]));
                mx1 = fmaxf(mx1, fmaxf(Sa[j][2], Sa[j][3]));
            }
            mx0 = fmaxf(mx0, __shfl_xor_sync(0xffffffffu, mx0, 1));
            mx0 = fmaxf(mx0, __shfl_xor_sync(0xffffffffu, mx0, 2));
            mx1 = fmaxf(mx1, __shfl_xor_sync(0xffffffffu, mx1, 1));
            mx1 = fmaxf(mx1, __shfl_xor_sync(0xffffffffu, mx1, 2));
            float mn0 = fmaxf(m_a0, alpha * mx0);
            float mn1 = fmaxf(m_a1, alpha * mx1);
            float sc0 = __expf(m_a0 - mn0);
            float sc1 = __expf(m_a1 - mn1);
            float s0 = 0.f, s1 = 0.f;
#pragma unroll
            for (int j = 0; j < 16; j++) {
                Sa[j][0] = __expf(fmaf(alpha, Sa[j][0], -mn0));
                Sa[j][1] = __expf(fmaf(alpha, Sa[j][1], -mn0));
                Sa[j][2] = __expf(fmaf(alpha, Sa[j][2], -mn1));
                Sa[j][3] = __expf(fmaf(alpha, Sa[j][3], -mn1));
                s0 += Sa[j][0] + Sa[j][1];
                s1 += Sa[j][2] + Sa[j][3];
            }
            l_a0 = l_a0 * sc0 + s0;
            l_a1 = l_a1 * sc1 + s1;
#pragma unroll
            for (int g = 0; g < 32; g++) {
                out[g][0] *= sc0; out[g][1] *= sc0;
                out[g][2] *= sc1; out[g][3] *= sc1;
            }
            m_a0 = mn0; m_a1 = mn1;
        }

        // ---- out += P . v^T  (4 v chunks of 32 tokens) ----
#pragma unroll
        for (int cv = 0; cv < 4; cv++) {
            if (kti == 31 && cv == 3) CPWAIT0(); else CPWAIT1();
            __syncthreads();
            if (s_kti < 32) FSTAGE();
            uint32_t bs = sring + (uint32_t)c_buf * CHUNK_BYTES;
            if (++c_buf == 3) c_buf = 0;

#pragma unroll
            for (int ks = 0; ks < 2; ks++) {
                int jj = cv * 2 + ks;
                unsigned a0 = pkbf(Sa[2 * jj][0],     Sa[2 * jj][1]);
                unsigned a1 = pkbf(Sa[2 * jj][2],     Sa[2 * jj][3]);
                unsigned a2 = pkbf(Sa[2 * jj + 1][0], Sa[2 * jj + 1][1]);
                unsigned a3 = pkbf(Sa[2 * jj + 1][2], Sa[2 * jj + 1][3]);
#pragma unroll
                for (int ng = 0; ng < 16; ng++) {
                    unsigned b0, b1, b2, b3;
                    LDSM4(b0, b1, b2, b3,
                          bs + (uint32_t)((ng * 16 + brow_l) * CSTR
                                          + ks * 16 + bkof_l) * 2);
                    mma16816(out[2 * ng],     a0, a1, a2, a3, b0, b1);
                    mma16816(out[2 * ng + 1], a0, a1, a2, a3, b2, b3);
                }
            }
        }
    }
#undef FSTAGE

    // ---- epilogue: finish l reduction, normalize, write bf16 aoT ----
    l_a0 += __shfl_xor_sync(0xffffffffu, l_a0, 1);
    l_a0 += __shfl_xor_sync(0xffffffffu, l_a0, 2);
    l_a1 += __shfl_xor_sync(0xffffffffu, l_a1, 1);
    l_a1 += __shfl_xor_sync(0xffffffffu, l_a1, 2);
    float i0 = 1.f / l_a0, i1 = 1.f / l_a1;

    bf16* ao = aoT + z * CHB;
    int r0 = q0 + wid * 16 + lr;
#pragma unroll
    for (int g = 0; g < 32; g++) {
        int col = g * 8 + 2 * lc;
        *(uint32_t*)&ao[(size_t)r0 * NCH + col]       = pkbf(out[g][0] * i0, out[g][1] * i0);
        *(uint32_t*)&ao[(size_t)(r0 + 8) * NCH + col] = pkbf(out[g][2] * i1, out[g][3] * i1);
    }
}

// ---------------------------------------------------------------------------
// kernel_launch — scratch via cudaGetSymbolAddress (true device addresses).
// ---------------------------------------------------------------------------
extern "C" void kernel_launch(void* const* d_in, const int* in_sizes, int n_in,
                              void* d_out, int out_size)
{
    const float* x   = (const float*)d_in[0];
    const float* gns = (const float*)d_in[1];
    const float* gnb = (const float*)d_in[2];
    const float* wq  = (const float*)d_in[3];
    const float* bq  = (const float*)d_in[4];
    const float* wk  = (const float*)d_in[5];
    const float* bk  = (const float*)d_in[6];
    const float* wv  = (const float*)d_in[7];
    const float* bv  = (const float*)d_in[8];
    const float* wo  = (const float*)d_in[9];
    const float* bo  = (const float*)d_in[10];
    float* out = (float*)d_out;

    void *p_hn, *p_hnT, *p_qT, *p_kT, *p_v, *p_aoT, *p_wb;
    cudaGetSymbolAddress(&p_hn,  g_hn);
    cudaGetSymbolAddress(&p_hnT, g_hnT);
    cudaGetSymbolAddress(&p_qT,  g_qT);
    cudaGetSymbolAddress(&p_kT,  g_kT);
    cudaGetSymbolAddress(&p_v,   g_v);
    cudaGetSymbolAddress(&p_aoT, g_aoT);
    cudaGetSymbolAddress(&p_wb,  g_wb);
    float*  hn  = (float*)p_hn;
    bf16*   hnT = (bf16*)p_hnT;
    bf16*   qT  = (bf16*)p_qT;
    bf16*   kT  = (bf16*)p_kT;
    bf16*   v   = (bf16*)p_v;
    bf16*   aoT = (bf16*)p_aoT;
    bf16*   wb  = (bf16*)p_wb;

    cudaFuncSetAttribute(hgemm<1, 2, 0>, cudaFuncAttributeMaxDynamicSharedMemorySize, SMEM_DYN);
    cudaFuncSetAttribute(hgemm<1, 1, 0>, cudaFuncAttributeMaxDynamicSharedMemorySize, SMEM_DYN);
    cudaFuncSetAttribute(hgemm<0, 1, 1>, cudaFuncAttributeMaxDynamicSharedMemorySize, SMEM_DYN);
    cudaFuncSetAttribute(attn_fused, cudaFuncAttributeMaxDynamicSharedMemorySize, FSMEM);

    // 0) bf16 weights + GroupNorm + hnT
    prep_kernel<<<256, 256>>>(wq, wk, wv, wo, wb);
    groupnorm_kernel<<<NB * 32, 256>>>(x, gns, gnb, hn);
    transpose_bf16_kernel<<<dim3(NTOK / 32, NCH / 32, NB), 256>>>(hn, hnT);

    // 1) qT[tok][ch] = hnT . wq^T + bq (per-col); kT likewise
    hgemm<1, 2, 0><<<dim3(2, 32, NB), 256, SMEM_DYN>>>(
        hnT, wb, qT, bq, nullptr, 1.f, 1.f,
        NTOK, NCH, NCH, CHB, 0, CHB);
    hgemm<1, 2, 0><<<dim3(2, 32, NB), 256, SMEM_DYN>>>(
        hnT, wb + 65536, kT, bk, nullptr, 1.f, 1.f,
        NTOK, NCH, NCH, CHB, 0, CHB);
    // v[ch][tok] = wv . hnT^T + bv (per-row)
    hgemm<1, 1, 0><<<dim3(32, 2, NB), 256, SMEM_DYN>>>(
        wb + 131072, hnT, v, bv, nullptr, 1.f, 1.f,
        NCH, NTOK, NCH, 0, CHB, CHB);

    // 2) fused attention: aoT[q][ch] = softmax((1/16) qT.kT^T) . v^T
    attn_fused<<<dim3(32, NB), 256, FSMEM>>>(qT, kT, v, aoT);

    // 3) out[ch][tok] = (wo . aoT^T + bo + x) / sqrt(2)
    hgemm<0, 1, 1><<<dim3(32, 2, NB), 256, SMEM_DYN>>>(
        wb + 196608, aoT, out, bo, x, 1.f, 0.70710678118654752f,
        NCH, NTOK, NCH, 0, CHB, CHB);
}

// round 11
// speedup vs baseline: 57.5782x; 1.1201x over previous
#include <cuda_runtime.h>
#include <cuda_bf16.h>
#include <cstdint>
#include <cstddef>

// Problem constants
#define NB    8
#define NCH   256
#define NTOK  4096
#define CHB   ((size_t)NCH * NTOK)

typedef __nv_bfloat16 bf16;

// Static scratch — accessed ONLY via cudaGetSymbolAddress-resolved pointers.
__device__ __align__(256) float  g_hn [NB * CHB];   // groupnorm out fp32 [ch][tok]
__device__ __align__(256) bf16   g_hnT[NB * CHB];   // [tok][ch]
__device__ __align__(256) bf16   g_qT [NB * CHB];   // [tok][ch]
__device__ __align__(256) bf16   g_kT [NB * CHB];   // [tok][ch]
__device__ __align__(256) bf16   g_v  [NB * CHB];   // [ch][tok]
__device__ __align__(256) bf16   g_aoT[NB * CHB];   // [tok][ch]
__device__ __align__(256) bf16   g_wb [4 * NCH * NCH]; // bf16 weights q,k,v,o

// ---------------------------------------------------------------------------
// common PTX helpers
// ---------------------------------------------------------------------------
__device__ __forceinline__ void mma16816(float* c, unsigned a0, unsigned a1,
                                         unsigned a2, unsigned a3,
                                         unsigned b0, unsigned b1)
{
    asm volatile(
        "mma.sync.aligned.m16n8k16.row.col.f32.bf16.bf16.f32 "
        "{%0,%1,%2,%3},{%4,%5,%6,%7},{%8,%9},{%0,%1,%2,%3};"
        : "+f"(c[0]), "+f"(c[1]), "+f"(c[2]), "+f"(c[3])
        : "r"(a0), "r"(a1), "r"(a2), "r"(a3), "r"(b0), "r"(b1));
}

#define LDSM4(r0, r1, r2, r3, addr) \
    asm volatile("ldmatrix.sync.aligned.m8n8.x4.shared.b16 {%0,%1,%2,%3}, [%4];" \
                 : "=r"(r0), "=r"(r1), "=r"(r2), "=r"(r3) : "r"(addr))

#define CP16(dst, src) \
    asm volatile("cp.async.cg.shared.global [%0], [%1], 16;" :: "r"(dst), "l"(src))
#define CPCOMMIT() asm volatile("cp.async.commit_group;" ::: "memory")
#define CPWAIT1()  asm volatile("cp.async.wait_group 1;" ::: "memory")
#define CPWAIT0()  asm volatile("cp.async.wait_group 0;" ::: "memory")

__device__ __forceinline__ unsigned pkbf(float x, float y) {
    __nv_bfloat162 h = __floats2bfloat162_rn(x, y);
    return *(unsigned*)&h;
}

// ---------------------------------------------------------------------------
// prep: weights fp32 -> bf16
// ---------------------------------------------------------------------------
__global__ __launch_bounds__(256) void prep_kernel(
    const float* __restrict__ wq, const float* __restrict__ wk,
    const float* __restrict__ wv, const float* __restrict__ wo,
    bf16* __restrict__ wb)
{
    int i = blockIdx.x * 256 + threadIdx.x;  // 65536
    wb[i]          = __float2bfloat16(wq[i]);
    wb[ 65536 + i] = __float2bfloat16(wk[i]);
    wb[131072 + i] = __float2bfloat16(wv[i]);
    wb[196608 + i] = __float2bfloat16(wo[i]);
}

// ---------------------------------------------------------------------------
// GroupNorm (proven, fp32 out)
// ---------------------------------------------------------------------------
__global__ __launch_bounds__(256) void groupnorm_kernel(
    const float* __restrict__ x, const float* __restrict__ sc,
    const float* __restrict__ bi, float* __restrict__ out)
{
    int b = blockIdx.x >> 5;
    int g = blockIdx.x & 31;
    size_t base = ((size_t)b * NCH + (size_t)g * 8) * NTOK;
    const float4* px = (const float4*)(x + base);
    float4* po = (float4*)(out + base);
    int t = threadIdx.x;

    float s = 0.f, ss = 0.f;
#pragma unroll
    for (int r = 0; r < 32; r++) {
        float4 f = px[r * 256 + t];
        s  += f.x + f.y + f.z + f.w;
        ss += f.x * f.x + f.y * f.y + f.z * f.z + f.w * f.w;
    }
#pragma unroll
    for (int o = 16; o; o >>= 1) {
        s  += __shfl_xor_sync(0xffffffffu, s, o);
        ss += __shfl_xor_sync(0xffffffffu, ss, o);
    }
    __shared__ float rs[8], rss[8];
    __shared__ float s_mean, s_rstd;
    if ((t & 31) == 0) { rs[t >> 5] = s; rss[t >> 5] = ss; }
    __syncthreads();
    if (t == 0) {
        float S = 0.f, SS = 0.f;
#pragma unroll
        for (int i = 0; i < 8; i++) { S += rs[i]; SS += rss[i]; }
        float m = S * (1.f / 32768.f);
        float var = SS * (1.f / 32768.f) - m * m;
        s_mean = m;
        s_rstd = rsqrtf(var + 1e-6f);
    }
    __syncthreads();
    float m = s_mean, rstd = s_rstd;
#pragma unroll
    for (int r = 0; r < 32; r++) {
        int idx = r * 256 + t;
        int c = g * 8 + (idx >> 10);
        float a = sc[c] * rstd;
        float bb = bi[c] - m * a;
        float4 f = px[idx];
        po[idx] = make_float4(f.x * a + bb, f.y * a + bb, f.z * a + bb, f.w * a + bb);
    }
}

// ---------------------------------------------------------------------------
// Transpose hn [256][4096] fp32 -> hnT [4096][256] bf16
// ---------------------------------------------------------------------------
__global__ __launch_bounds__(256) void transpose_bf16_kernel(
    const float* __restrict__ in, bf16* __restrict__ out)
{
    __shared__ float tile[32][33];
    size_t z = blockIdx.z;
    const float* ip = in + z * CHB;
    bf16* op = out + z * CHB;
    int n0 = blockIdx.x * 32, c0 = blockIdx.y * 32;
    int tx = threadIdx.x & 31, ty = threadIdx.x >> 5;
#pragma unroll
    for (int j = 0; j < 32; j += 8)
        tile[ty + j][tx] = ip[(size_t)(c0 + ty + j) * NTOK + n0 + tx];
    __syncthreads();
#pragma unroll
    for (int j = 0; j < 32; j += 8)
        op[(size_t)(n0 + ty + j) * NCH + c0 + tx] = __float2bfloat16(tile[tx][ty + j]);
}

// ---------------------------------------------------------------------------
// hgemm: warp-MMA bf16 GEMM, 3-stage cp.async pipeline (round-9 proven).
// ---------------------------------------------------------------------------
#define ASTRB 40
#define OPB   (128 * ASTRB * 2)
#define BUFB  (2 * OPB)
#define SMEM_DYN (3 * BUFB)

template<int OUT_MODE, int BIAS_MODE, int RESID>   // OUT_MODE: 0 fp32, 1 bf16
__global__ __launch_bounds__(256, 2) void hgemm(
    const bf16* __restrict__ A, const bf16* __restrict__ B,
    void* __restrict__ Cout, const float* __restrict__ bias,
    const float* __restrict__ resid, float alpha, float outscale,
    int M, int N, int K, size_t bA, size_t bB, size_t bC)
{
    extern __shared__ char dynsm[];
    uint32_t sBase = (uint32_t)__cvta_generic_to_shared(dynsm);

    int t = threadIdx.x;
    int m0 = blockIdx.y * 128, n0 = blockIdx.x * 128;
    size_t z = blockIdx.z;

    int wid = t >> 5, lane = t & 31;
    int mw = (wid & 1) * 64, nw = (wid >> 1) * 32;
    int lr = lane >> 2, lc = lane & 3;

    float acc[64];
#pragma unroll
    for (int i = 0; i < 64; i++) acc[i] = 0.f;

    int rowa = t >> 2, gcol = t & 3;
    const bf16* Ab = A + z * bA + (size_t)(m0 + rowa) * K + gcol * 8;
    const bf16* Bb = B + z * bB + (size_t)(n0 + rowa) * K + gcol * 8;
    size_t rstep = (size_t)64 * K;

    uint32_t stOff   = (uint32_t)(rowa * ASTRB + gcol * 8) * 2;
    uint32_t stOff64 = stOff + (uint32_t)(64 * ASTRB) * 2;

    int arow_l = (lane & 7) + ((lane >> 3) & 1) * 8;
    int akof_l = (lane >> 4) * 8;
    int brow_l = (lane & 7) + ((lane >> 4) & 1) * 8;
    int bkof_l = ((lane >> 3) & 1) * 8;

    int nkt = K / 32;

#define STAGE(chunk, buf) do {                                        \
        size_t go = (size_t)(chunk) * 32;                             \
        uint32_t ab = sBase + (uint32_t)(buf) * BUFB;                 \
        uint32_t bb2 = ab + OPB;                                      \
        CP16(ab + stOff,    Ab + go);                                 \
        CP16(ab + stOff64,  Ab + go + rstep);                         \
        CP16(bb2 + stOff,   Bb + go);                                 \
        CP16(bb2 + stOff64, Bb + go + rstep);                         \
        CPCOMMIT();                                                   \
    } while (0)

    STAGE(0, 0);
    STAGE(1, 1);

    int buf = 0;
    for (int kt = 0; kt < nkt; kt++) {
        if (kt + 1 < nkt) CPWAIT1(); else CPWAIT0();
        __syncthreads();

        if (kt + 2 < nkt) {
            int nb = buf + 2; if (nb >= 3) nb -= 3;
            STAGE(kt + 2, nb);
        }

        uint32_t aBuf = sBase + (uint32_t)buf * BUFB;
        uint32_t bBuf = aBuf + OPB;
#pragma unroll
        for (int ks = 0; ks < 2; ks++) {
            int ko = ks * 16;
            unsigned bfr[4][2];
#pragma unroll
            for (int np = 0; np < 2; np++) {
                uint32_t ba = bBuf + (uint32_t)((nw + np * 16 + brow_l) * ASTRB
                                                + ko + bkof_l) * 2;
                LDSM4(bfr[np * 2][0], bfr[np * 2][1],
                      bfr[np * 2 + 1][0], bfr[np * 2 + 1][1], ba);
            }
#pragma unroll
            for (int mf = 0; mf < 4; mf++) {
                unsigned a0, a1, a2, a3;
                uint32_t aa = aBuf + (uint32_t)((mw + mf * 16 + arow_l) * ASTRB
                                                + ko + akof_l) * 2;
                LDSM4(a0, a1, a2, a3, aa);
#pragma unroll
                for (int nf = 0; nf < 4; nf++)
                    mma16816(acc + (mf * 4 + nf) * 4, a0, a1, a2, a3,
                             bfr[nf][0], bfr[nf][1]);
            }
        }
        if (++buf == 3) buf = 0;
    }
#undef STAGE

#pragma unroll
    for (int mf = 0; mf < 4; mf++) {
#pragma unroll
        for (int nf = 0; nf < 4; nf++) {
            float* c = acc + (mf * 4 + nf) * 4;
            int mg = m0 + mw + mf * 16 + lr;
            int ng = n0 + nw + nf * 8 + 2 * lc;
            float o0 = c[0] * alpha, o1 = c[1] * alpha;
            float o2 = c[2] * alpha, o3 = c[3] * alpha;
            if (BIAS_MODE == 1) {
                float b0 = bias[mg], b1 = bias[mg + 8];
                o0 += b0; o1 += b0; o2 += b1; o3 += b1;
            } else if (BIAS_MODE == 2) {
                float b0 = bias[ng], b1 = bias[ng + 1];
                o0 += b0; o1 += b1; o2 += b0; o3 += b1;
            }
            size_t i0 = (size_t)mg * N + ng;
            size_t i1 = (size_t)(mg + 8) * N + ng;
            if (RESID) {
                const float* Rb = resid + z * bC;
                o0 = (o0 + Rb[i0])     * outscale;
                o1 = (o1 + Rb[i0 + 1]) * outscale;
                o2 = (o2 + Rb[i1])     * outscale;
                o3 = (o3 + Rb[i1 + 1]) * outscale;
            }
            if (OUT_MODE == 1) {
                bf16* Cb = (bf16*)Cout + z * bC;
                *(uint32_t*)&Cb[i0] = pkbf(o0, o1);
                *(uint32_t*)&Cb[i1] = pkbf(o2, o3);
            } else {
                float* Cb = (float*)Cout + z * bC;
                float2 p0 = {o0, o1}, p1 = {o2, o3};
                *(float2*)&Cb[i0] = p0;
                *(float2*)&Cb[i1] = p1;
            }
        }
    }
}

// ---------------------------------------------------------------------------
// Fused flash attention v2: 4 big chunks per k-tile (vs 12 small).
//   chunk type 0/1: kT half-tile, 64 tokens x 256 ch (stride 264)
//   chunk type 2/3: v  half-tile, 256 ch x 64 tokens (stride 72)
// 128 barrier rounds total (vs 384). Ring of 3 x 36.9KB; q tile resident.
// ---------------------------------------------------------------------------
#define QSTR 264
#define KSTR 264
#define VSTR 72
#define Q_BYTES (128 * QSTR * 2)          // 67584
#define CHUNK_BYTES (256 * VSTR * 2)      // 36864 (>= 64*KSTR*2 = 33792)
#define FSMEM (Q_BYTES + 3 * CHUNK_BYTES) // 178176

__global__ __launch_bounds__(256, 1) void attn_fused(
    const bf16* __restrict__ qT, const bf16* __restrict__ kT,
    const bf16* __restrict__ vv, bf16* __restrict__ aoT)
{
    extern __shared__ char fsm[];
    const float alpha = 0.0625f;
    uint32_t sq = (uint32_t)__cvta_generic_to_shared(fsm);
    uint32_t sring = sq + Q_BYTES;

    int t = threadIdx.x, wid = t >> 5, lane = t & 31;
    int lr = lane >> 2, lc = lane & 3;
    size_t z = blockIdx.y;
    int q0 = blockIdx.x * 128;

    const bf16* qb = qT + z * CHB;
    const bf16* kb = kT + z * CHB;
    const bf16* vb = vv + z * CHB;

    int arow_l = (lane & 7) + ((lane >> 3) & 1) * 8;
    int akof_l = (lane >> 4) * 8;
    int brow_l = (lane & 7) + ((lane >> 4) & 1) * 8;
    int bkof_l = ((lane >> 3) & 1) * 8;

    // stage q tile (one commit group)
#pragma unroll
    for (int i = 0; i < 16; i++) {
        int idx = i * 256 + t;
        int row = idx >> 5, g = idx & 31;
        CP16(sq + (uint32_t)(row * QSTR + g * 8) * 2,
             qb + (size_t)(q0 + row) * NCH + g * 8);
    }
    CPCOMMIT();

    float out[32][4];
#pragma unroll
    for (int g = 0; g < 32; g++) {
        out[g][0] = 0.f; out[g][1] = 0.f; out[g][2] = 0.f; out[g][3] = 0.f;
    }
    float Sa[16][4];
    float m_a0 = -1e30f, m_a1 = -1e30f, l_a0 = 0.f, l_a1 = 0.f;

    // chunk staging: global chunk index s_idx in [0,128); type = s_idx&3
    int s_idx = 0;
#define FSTAGE() do {                                                       \
        int ty_ = s_idx & 3, kti_ = s_idx >> 2;                             \
        uint32_t bs = sring + (uint32_t)(s_idx % 3) * CHUNK_BYTES;          \
        if (ty_ < 2) {                                                      \
            const bf16* src = kb + (size_t)(kti_ * 128 + ty_ * 64) * NCH;   \
            _Pragma("unroll")                                               \
            for (int i = 0; i < 8; i++) {                                   \
                int idx = i * 256 + t; int row = idx >> 5, g = idx & 31;    \
                CP16(bs + (uint32_t)(row * KSTR + g * 8) * 2,               \
                     src + (size_t)row * NCH + g * 8);                      \
            }                                                               \
        } else {                                                            \
            const bf16* src = vb + kti_ * 128 + (ty_ - 2) * 64;             \
            _Pragma("unroll")                                               \
            for (int i = 0; i < 8; i++) {                                   \
                int idx = i * 256 + t; int row = idx >> 3, g = idx & 7;     \
                CP16(bs + (uint32_t)(row * VSTR + g * 8) * 2,               \
                     src + (size_t)row * NTOK + g * 8);                     \
            }                                                               \
        }                                                                   \
        CPCOMMIT();                                                         \
        s_idx++;                                                            \
    } while (0)

    FSTAGE();   // chunk 0
    FSTAGE();   // chunk 1

    int c_idx = 0;
    uint32_t bs_cur;
#define ADV() do {                                                          \
        if (c_idx < 127) CPWAIT1(); else CPWAIT0();                         \
        __syncthreads();                                                    \
        if (s_idx < 128) FSTAGE();                                          \
        bs_cur = sring + (uint32_t)(c_idx % 3) * CHUNK_BYTES;               \
        c_idx++;                                                            \
    } while (0)

    for (int kti = 0; kti < 32; kti++) {
        // ---- S = q . kT^T : two 64-token halves ----
#pragma unroll
        for (int h = 0; h < 2; h++) {
            ADV();
            if (h == 0) {
#pragma unroll
                for (int j = 0; j < 16; j++) {
                    Sa[j][0] = 0.f; Sa[j][1] = 0.f; Sa[j][2] = 0.f; Sa[j][3] = 0.f;
                }
            }
#pragma unroll
            for (int ks = 0; ks < 16; ks++) {
                unsigned a0, a1, a2, a3;
                LDSM4(a0, a1, a2, a3,
                      sq + (uint32_t)((wid * 16 + arow_l) * QSTR
                                      + ks * 16 + akof_l) * 2);
#pragma unroll
                for (int ng = 0; ng < 4; ng++) {
                    unsigned b0, b1, b2, b3;
                    LDSM4(b0, b1, b2, b3,
                          bs_cur + (uint32_t)((ng * 16 + brow_l) * KSTR
                                              + ks * 16 + bkof_l) * 2);
                    int j = h * 8 + 2 * ng;
                    mma16816(Sa[j],     a0, a1, a2, a3, b0, b1);
                    mma16816(Sa[j + 1], a0, a1, a2, a3, b2, b3);
                }
            }
        }

        // ---- online softmax update (quad shuffles only) ----
        {
            float mx0 = -1e30f, mx1 = -1e30f;
#pragma unroll
            for (int j = 0; j < 16; j++) {
                mx0 = fmaxf(mx0, fmaxf(Sa[j][0], Sa[j][1]));
                mx1 = fmaxf(mx1, fmaxf(Sa[j][2], Sa[j][3]));
            }
            mx0 = fmaxf(mx0, __shfl_xor_sync(0xffffffffu, mx0, 1));
            mx0 = fmaxf(mx0, __shfl_xor_sync(0xffffffffu, mx0, 2));
            mx1 = fmaxf(mx1, __shfl_xor_sync(0xffffffffu, mx1, 1));
            mx1 = fmaxf(mx1, __shfl_xor_sync(0xffffffffu, mx1, 2));
            float mn0 = fmaxf(m_a0, alpha * mx0);
            float mn1 = fmaxf(m_a1, alpha * mx1);
            float sc0 = __expf(m_a0 - mn0);
            float sc1 = __expf(m_a1 - mn1);
            float s0 = 0.f, s1 = 0.f;
#pragma unroll
            for (int j = 0; j < 16; j++) {
                Sa[j][0] = __expf(fmaf(alpha, Sa[j][0], -mn0));
                Sa[j][1] = __expf(fmaf(alpha, Sa[j][1], -mn0));
                Sa[j][2] = __expf(fmaf(alpha, Sa[j][2], -mn1));
                Sa[j][3] = __expf(fmaf(alpha, Sa[j][3], -mn1));
                s0 += Sa[j][0] + Sa[j][1];
                s1 += Sa[j][2] + Sa[j][3];
            }
            l_a0 = l_a0 * sc0 + s0;
            l_a1 = l_a1 * sc1 + s1;
#pragma unroll
            for (int g = 0; g < 32; g++) {
                out[g][0] *= sc0; out[g][1] *= sc0;
                out[g][2] *= sc1; out[g][3] *= sc1;
            }
            m_a0 = mn0; m_a1 = mn1;
        }

        // ---- out += P . v^T : two 64-token halves ----
#pragma unroll
        for (int h = 0; h < 2; h++) {
            ADV();
#pragma unroll
            for (int ks = 0; ks < 4; ks++) {
                int jj = h * 4 + ks;
                unsigned a0 = pkbf(Sa[2 * jj][0],     Sa[2 * jj][1]);
                unsigned a1 = pkbf(Sa[2 * jj][2],     Sa[2 * jj][3]);
                unsigned a2 = pkbf(Sa[2 * jj + 1][0], Sa[2 * jj + 1][1]);
                unsigned a3 = pkbf(Sa[2 * jj + 1][2], Sa[2 * jj + 1][3]);
#pragma unroll
                for (int ng = 0; ng < 16; ng++) {
                    unsigned b0, b1, b2, b3;
                    LDSM4(b0, b1, b2, b3,
                          bs_cur + (uint32_t)((ng * 16 + brow_l) * VSTR
                                              + ks * 16 + bkof_l) * 2);
                    mma16816(out[2 * ng],     a0, a1, a2, a3, b0, b1);
                    mma16816(out[2 * ng + 1], a0, a1, a2, a3, b2, b3);
                }
            }
        }
    }
#undef ADV
#undef FSTAGE

    // ---- epilogue: finish l reduction, normalize, write bf16 aoT ----
    l_a0 += __shfl_xor_sync(0xffffffffu, l_a0, 1);
    l_a0 += __shfl_xor_sync(0xffffffffu, l_a0, 2);
    l_a1 += __shfl_xor_sync(0xffffffffu, l_a1, 1);
    l_a1 += __shfl_xor_sync(0xffffffffu, l_a1, 2);
    float i0 = 1.f / l_a0, i1 = 1.f / l_a1;

    bf16* ao = aoT + z * CHB;
    int r0 = q0 + wid * 16 + lr;
#pragma unroll
    for (int g = 0; g < 32; g++) {
        int col = g * 8 + 2 * lc;
        *(uint32_t*)&ao[(size_t)r0 * NCH + col]       = pkbf(out[g][0] * i0, out[g][1] * i0);
        *(uint32_t*)&ao[(size_t)(r0 + 8) * NCH + col] = pkbf(out[g][2] * i1, out[g][3] * i1);
    }
}

// ---------------------------------------------------------------------------
// kernel_launch — scratch via cudaGetSymbolAddress (true device addresses).
// ---------------------------------------------------------------------------
extern "C" void kernel_launch(void* const* d_in, const int* in_sizes, int n_in,
                              void* d_out, int out_size)
{
    const float* x   = (const float*)d_in[0];
    const float* gns = (const float*)d_in[1];
    const float* gnb = (const float*)d_in[2];
    const float* wq  = (const float*)d_in[3];
    const float* bq  = (const float*)d_in[4];
    const float* wk  = (const float*)d_in[5];
    const float* bk  = (const float*)d_in[6];
    const float* wv  = (const float*)d_in[7];
    const float* bv  = (const float*)d_in[8];
    const float* wo  = (const float*)d_in[9];
    const float* bo  = (const float*)d_in[10];
    float* out = (float*)d_out;

    void *p_hn, *p_hnT, *p_qT, *p_kT, *p_v, *p_aoT, *p_wb;
    cudaGetSymbolAddress(&p_hn,  g_hn);
    cudaGetSymbolAddress(&p_hnT, g_hnT);
    cudaGetSymbolAddress(&p_qT,  g_qT);
    cudaGetSymbolAddress(&p_kT,  g_kT);
    cudaGetSymbolAddress(&p_v,   g_v);
    cudaGetSymbolAddress(&p_aoT, g_aoT);
    cudaGetSymbolAddress(&p_wb,  g_wb);
    float*  hn  = (float*)p_hn;
    bf16*   hnT = (bf16*)p_hnT;
    bf16*   qT  = (bf16*)p_qT;
    bf16*   kT  = (bf16*)p_kT;
    bf16*   v   = (bf16*)p_v;
    bf16*   aoT = (bf16*)p_aoT;
    bf16*   wb  = (bf16*)p_wb;

    cudaFuncSetAttribute(hgemm<1, 2, 0>, cudaFuncAttributeMaxDynamicSharedMemorySize, SMEM_DYN);
    cudaFuncSetAttribute(hgemm<1, 1, 0>, cudaFuncAttributeMaxDynamicSharedMemorySize, SMEM_DYN);
    cudaFuncSetAttribute(hgemm<0, 1, 1>, cudaFuncAttributeMaxDynamicSharedMemorySize, SMEM_DYN);
    cudaFuncSetAttribute(attn_fused, cudaFuncAttributeMaxDynamicSharedMemorySize, FSMEM);

    // 0) bf16 weights + GroupNorm + hnT
    prep_kernel<<<256, 256>>>(wq, wk, wv, wo, wb);
    groupnorm_kernel<<<NB * 32, 256>>>(x, gns, gnb, hn);
    transpose_bf16_kernel<<<dim3(NTOK / 32, NCH / 32, NB), 256>>>(hn, hnT);

    // 1) qT[tok][ch] = hnT . wq^T + bq (per-col); kT likewise
    hgemm<1, 2, 0><<<dim3(2, 32, NB), 256, SMEM_DYN>>>(
        hnT, wb, qT, bq, nullptr, 1.f, 1.f,
        NTOK, NCH, NCH, CHB, 0, CHB);
    hgemm<1, 2, 0><<<dim3(2, 32, NB), 256, SMEM_DYN>>>(
        hnT, wb + 65536, kT, bk, nullptr, 1.f, 1.f,
        NTOK, NCH, NCH, CHB, 0, CHB);
    // v[ch][tok] = wv . hnT^T + bv (per-row)
    hgemm<1, 1, 0><<<dim3(32, 2, NB), 256, SMEM_DYN>>>(
        wb + 131072, hnT, v, bv, nullptr, 1.f, 1.f,
        NCH, NTOK, NCH, 0, CHB, CHB);

    // 2) fused attention: aoT[q][ch] = softmax((1/16) qT.kT^T) . v^T
    attn_fused<<<dim3(32, NB), 256, FSMEM>>>(qT, kT, v, aoT);

    // 3) out[ch][tok] = (wo . aoT^T + bo + x) / sqrt(2)
    hgemm<0, 1, 1><<<dim3(32, 2, NB), 256, SMEM_DYN>>>(
        wb + 196608, aoT, out, bo, x, 1.f, 0.70710678118654752f,
        NCH, NTOK, NCH, 0, CHB, CHB);
}

// round 12
// speedup vs baseline: 59.3588x; 1.0309x over previous
#include <cuda_runtime.h>
#include <cuda_bf16.h>
#include <cuda_fp16.h>
#include <cstdint>
#include <cstddef>

// Problem constants
#define NB    8
#define NCH   256
#define NTOK  4096
#define CHB   ((size_t)NCH * NTOK)

typedef __nv_bfloat16 bf16;

// Static scratch — accessed ONLY via cudaGetSymbolAddress-resolved pointers.
__device__ __align__(256) float  g_hn [NB * CHB];   // groupnorm out fp32 [ch][tok]
__device__ __align__(256) bf16   g_hnT[NB * CHB];   // [tok][ch] bf16
__device__ __align__(256) __half g_qT [NB * CHB];   // [tok][ch] fp16
__device__ __align__(256) __half g_kT [NB * CHB];   // [tok][ch] fp16
__device__ __align__(256) __half g_v  [NB * CHB];   // [ch][tok] fp16
__device__ __align__(256) bf16   g_aoT[NB * CHB];   // [tok][ch] bf16
__device__ __align__(256) bf16   g_wb [4 * NCH * NCH]; // bf16 weights q,k,v,o

// ---------------------------------------------------------------------------
// common PTX helpers
// ---------------------------------------------------------------------------
__device__ __forceinline__ void mma16816(float* c, unsigned a0, unsigned a1,
                                         unsigned a2, unsigned a3,
                                         unsigned b0, unsigned b1)
{
    asm volatile(
        "mma.sync.aligned.m16n8k16.row.col.f32.bf16.bf16.f32 "
        "{%0,%1,%2,%3},{%4,%5,%6,%7},{%8,%9},{%0,%1,%2,%3};"
        : "+f"(c[0]), "+f"(c[1]), "+f"(c[2]), "+f"(c[3])
        : "r"(a0), "r"(a1), "r"(a2), "r"(a3), "r"(b0), "r"(b1));
}

// fp16 operands, fp32 accumulate (PV + l)
__device__ __forceinline__ void mma16816h(float* c, unsigned a0, unsigned a1,
                                          unsigned a2, unsigned a3,
                                          unsigned b0, unsigned b1)
{
    asm volatile(
        "mma.sync.aligned.m16n8k16.row.col.f32.f16.f16.f32 "
        "{%0,%1,%2,%3},{%4,%5,%6,%7},{%8,%9},{%0,%1,%2,%3};"
        : "+f"(c[0]), "+f"(c[1]), "+f"(c[2]), "+f"(c[3])
        : "r"(a0), "r"(a1), "r"(a2), "r"(a3), "r"(b0), "r"(b1));
}

// fp16 operands, fp16 accumulate (S logits)
__device__ __forceinline__ void mma16816hh(unsigned* c, unsigned a0, unsigned a1,
                                           unsigned a2, unsigned a3,
                                           unsigned b0, unsigned b1)
{
    asm volatile(
        "mma.sync.aligned.m16n8k16.row.col.f16.f16.f16.f16 "
        "{%0,%1},{%2,%3,%4,%5},{%6,%7},{%0,%1};"
        : "+r"(c[0]), "+r"(c[1])
        : "r"(a0), "r"(a1), "r"(a2), "r"(a3), "r"(b0), "r"(b1));
}

#define LDSM4(r0, r1, r2, r3, addr) \
    asm volatile("ldmatrix.sync.aligned.m8n8.x4.shared.b16 {%0,%1,%2,%3}, [%4];" \
                 : "=r"(r0), "=r"(r1), "=r"(r2), "=r"(r3) : "r"(addr))

#define CP16(dst, src) \
    asm volatile("cp.async.cg.shared.global [%0], [%1], 16;" :: "r"(dst), "l"(src))
#define CPCOMMIT() asm volatile("cp.async.commit_group;" ::: "memory")
#define CPWAIT1()  asm volatile("cp.async.wait_group 1;" ::: "memory")
#define CPWAIT0()  asm volatile("cp.async.wait_group 0;" ::: "memory")

__device__ __forceinline__ unsigned pkbf(float x, float y) {
    __nv_bfloat162 h = __floats2bfloat162_rn(x, y);
    return *(unsigned*)&h;
}
__device__ __forceinline__ unsigned pkh(float x, float y) {
    __half2 h = __floats2half2_rn(x, y);
    return *(unsigned*)&h;
}

// ---------------------------------------------------------------------------
// prep: weights fp32 -> bf16
// ---------------------------------------------------------------------------
__global__ __launch_bounds__(256) void prep_kernel(
    const float* __restrict__ wq, const float* __restrict__ wk,
    const float* __restrict__ wv, const float* __restrict__ wo,
    bf16* __restrict__ wb)
{
    int i = blockIdx.x * 256 + threadIdx.x;  // 65536
    wb[i]          = __float2bfloat16(wq[i]);
    wb[ 65536 + i] = __float2bfloat16(wk[i]);
    wb[131072 + i] = __float2bfloat16(wv[i]);
    wb[196608 + i] = __float2bfloat16(wo[i]);
}

// ---------------------------------------------------------------------------
// GroupNorm (proven, fp32 out)
// ---------------------------------------------------------------------------
__global__ __launch_bounds__(256) void groupnorm_kernel(
    const float* __restrict__ x, const float* __restrict__ sc,
    const float* __restrict__ bi, float* __restrict__ out)
{
    int b = blockIdx.x >> 5;
    int g = blockIdx.x & 31;
    size_t base = ((size_t)b * NCH + (size_t)g * 8) * NTOK;
    const float4* px = (const float4*)(x + base);
    float4* po = (float4*)(out + base);
    int t = threadIdx.x;

    float s = 0.f, ss = 0.f;
#pragma unroll
    for (int r = 0; r < 32; r++) {
        float4 f = px[r * 256 + t];
        s  += f.x + f.y + f.z + f.w;
        ss += f.x * f.x + f.y * f.y + f.z * f.z + f.w * f.w;
    }
#pragma unroll
    for (int o = 16; o; o >>= 1) {
        s  += __shfl_xor_sync(0xffffffffu, s, o);
        ss += __shfl_xor_sync(0xffffffffu, ss, o);
    }
    __shared__ float rs[8], rss[8];
    __shared__ float s_mean, s_rstd;
    if ((t & 31) == 0) { rs[t >> 5] = s; rss[t >> 5] = ss; }
    __syncthreads();
    if (t == 0) {
        float S = 0.f, SS = 0.f;
#pragma unroll
        for (int i = 0; i < 8; i++) { S += rs[i]; SS += rss[i]; }
        float m = S * (1.f / 32768.f);
        float var = SS * (1.f / 32768.f) - m * m;
        s_mean = m;
        s_rstd = rsqrtf(var + 1e-6f);
    }
    __syncthreads();
    float m = s_mean, rstd = s_rstd;
#pragma unroll
    for (int r = 0; r < 32; r++) {
        int idx = r * 256 + t;
        int c = g * 8 + (idx >> 10);
        float a = sc[c] * rstd;
        float bb = bi[c] - m * a;
        float4 f = px[idx];
        po[idx] = make_float4(f.x * a + bb, f.y * a + bb, f.z * a + bb, f.w * a + bb);
    }
}

// ---------------------------------------------------------------------------
// Transpose hn [256][4096] fp32 -> hnT [4096][256] bf16
// ---------------------------------------------------------------------------
__global__ __launch_bounds__(256) void transpose_bf16_kernel(
    const float* __restrict__ in, bf16* __restrict__ out)
{
    __shared__ float tile[32][33];
    size_t z = blockIdx.z;
    const float* ip = in + z * CHB;
    bf16* op = out + z * CHB;
    int n0 = blockIdx.x * 32, c0 = blockIdx.y * 32;
    int tx = threadIdx.x & 31, ty = threadIdx.x >> 5;
#pragma unroll
    for (int j = 0; j < 32; j += 8)
        tile[ty + j][tx] = ip[(size_t)(c0 + ty + j) * NTOK + n0 + tx];
    __syncthreads();
#pragma unroll
    for (int j = 0; j < 32; j += 8)
        op[(size_t)(n0 + ty + j) * NCH + c0 + tx] = __float2bfloat16(tile[tx][ty + j]);
}

// ---------------------------------------------------------------------------
// hgemm: warp-MMA bf16 GEMM, 3-stage cp.async pipeline (round-9 proven).
// OUT_MODE: 0 fp32, 1 bf16, 2 fp16.
// ---------------------------------------------------------------------------
#define ASTRB 40
#define OPB   (128 * ASTRB * 2)
#define BUFB  (2 * OPB)
#define SMEM_DYN (3 * BUFB)

template<int OUT_MODE, int BIAS_MODE, int RESID>
__global__ __launch_bounds__(256, 2) void hgemm(
    const bf16* __restrict__ A, const bf16* __restrict__ B,
    void* __restrict__ Cout, const float* __restrict__ bias,
    const float* __restrict__ resid, float alpha, float outscale,
    int M, int N, int K, size_t bA, size_t bB, size_t bC)
{
    extern __shared__ char dynsm[];
    uint32_t sBase = (uint32_t)__cvta_generic_to_shared(dynsm);

    int t = threadIdx.x;
    int m0 = blockIdx.y * 128, n0 = blockIdx.x * 128;
    size_t z = blockIdx.z;

    int wid = t >> 5, lane = t & 31;
    int mw = (wid & 1) * 64, nw = (wid >> 1) * 32;
    int lr = lane >> 2, lc = lane & 3;

    float acc[64];
#pragma unroll
    for (int i = 0; i < 64; i++) acc[i] = 0.f;

    int rowa = t >> 2, gcol = t & 3;
    const bf16* Ab = A + z * bA + (size_t)(m0 + rowa) * K + gcol * 8;
    const bf16* Bb = B + z * bB + (size_t)(n0 + rowa) * K + gcol * 8;
    size_t rstep = (size_t)64 * K;

    uint32_t stOff   = (uint32_t)(rowa * ASTRB + gcol * 8) * 2;
    uint32_t stOff64 = stOff + (uint32_t)(64 * ASTRB) * 2;

    int arow_l = (lane & 7) + ((lane >> 3) & 1) * 8;
    int akof_l = (lane >> 4) * 8;
    int brow_l = (lane & 7) + ((lane >> 4) & 1) * 8;
    int bkof_l = ((lane >> 3) & 1) * 8;

    int nkt = K / 32;

#define STAGE(chunk, buf) do {                                        \
        size_t go = (size_t)(chunk) * 32;                             \
        uint32_t ab = sBase + (uint32_t)(buf) * BUFB;                 \
        uint32_t bb2 = ab + OPB;                                      \
        CP16(ab + stOff,    Ab + go);                                 \
        CP16(ab + stOff64,  Ab + go + rstep);                         \
        CP16(bb2 + stOff,   Bb + go);                                 \
        CP16(bb2 + stOff64, Bb + go + rstep);                         \
        CPCOMMIT();                                                   \
    } while (0)

    STAGE(0, 0);
    STAGE(1, 1);

    int buf = 0;
    for (int kt = 0; kt < nkt; kt++) {
        if (kt + 1 < nkt) CPWAIT1(); else CPWAIT0();
        __syncthreads();

        if (kt + 2 < nkt) {
            int nb = buf + 2; if (nb >= 3) nb -= 3;
            STAGE(kt + 2, nb);
        }

        uint32_t aBuf = sBase + (uint32_t)buf * BUFB;
        uint32_t bBuf = aBuf + OPB;
#pragma unroll
        for (int ks = 0; ks < 2; ks++) {
            int ko = ks * 16;
            unsigned bfr[4][2];
#pragma unroll
            for (int np = 0; np < 2; np++) {
                uint32_t ba = bBuf + (uint32_t)((nw + np * 16 + brow_l) * ASTRB
                                                + ko + bkof_l) * 2;
                LDSM4(bfr[np * 2][0], bfr[np * 2][1],
                      bfr[np * 2 + 1][0], bfr[np * 2 + 1][1], ba);
            }
#pragma unroll
            for (int mf = 0; mf < 4; mf++) {
                unsigned a0, a1, a2, a3;
                uint32_t aa = aBuf + (uint32_t)((mw + mf * 16 + arow_l) * ASTRB
                                                + ko + akof_l) * 2;
                LDSM4(a0, a1, a2, a3, aa);
#pragma unroll
                for (int nf = 0; nf < 4; nf++)
                    mma16816(acc + (mf * 4 + nf) * 4, a0, a1, a2, a3,
                             bfr[nf][0], bfr[nf][1]);
            }
        }
        if (++buf == 3) buf = 0;
    }
#undef STAGE

#pragma unroll
    for (int mf = 0; mf < 4; mf++) {
#pragma unroll
        for (int nf = 0; nf < 4; nf++) {
            float* c = acc + (mf * 4 + nf) * 4;
            int mg = m0 + mw + mf * 16 + lr;
            int ng = n0 + nw + nf * 8 + 2 * lc;
            float o0 = c[0] * alpha, o1 = c[1] * alpha;
            float o2 = c[2] * alpha, o3 = c[3] * alpha;
            if (BIAS_MODE == 1) {
                float b0 = bias[mg], b1 = bias[mg + 8];
                o0 += b0; o1 += b0; o2 += b1; o3 += b1;
            } else if (BIAS_MODE == 2) {
                float b0 = bias[ng], b1 = bias[ng + 1];
                o0 += b0; o1 += b1; o2 += b0; o3 += b1;
            }
            size_t i0 = (size_t)mg * N + ng;
            size_t i1 = (size_t)(mg + 8) * N + ng;
            if (RESID) {
                const float* Rb = resid + z * bC;
                o0 = (o0 + Rb[i0])     * outscale;
                o1 = (o1 + Rb[i0 + 1]) * outscale;
                o2 = (o2 + Rb[i1])     * outscale;
                o3 = (o3 + Rb[i1 + 1]) * outscale;
            }
            if (OUT_MODE == 1) {
                bf16* Cb = (bf16*)Cout + z * bC;
                *(uint32_t*)&Cb[i0] = pkbf(o0, o1);
                *(uint32_t*)&Cb[i1] = pkbf(o2, o3);
            } else if (OUT_MODE == 2) {
                __half* Cb = (__half*)Cout + z * bC;
                *(uint32_t*)&Cb[i0] = pkh(o0, o1);
                *(uint32_t*)&Cb[i1] = pkh(o2, o3);
            } else {
                float* Cb = (float*)Cout + z * bC;
                float2 p0 = {o0, o1}, p1 = {o2, o3};
                *(float2*)&Cb[i0] = p0;
                *(float2*)&Cb[i1] = p1;
            }
        }
    }
}

// ---------------------------------------------------------------------------
// Fused flash attention v3 — fp16 S-path.
//   S: fp16 operands, fp16 accumulate (Sa2 = 2 regs per n8-group).
//   softmax: exp2 domain, half2 math; P emerges pre-packed as PV A-frags.
//   l: ones-column MMA into fp32 C (rescales with out -> exact online softmax).
//   PV: fp16 operands, fp32 accumulate.
// Chunk/ring/staging identical to round-11 (proven).
// ---------------------------------------------------------------------------
#define QSTR 264
#define KSTR 264
#define VSTR 72
#define Q_BYTES (128 * QSTR * 2)          // 67584
#define CHUNK_BYTES (256 * VSTR * 2)      // 36864
#define FSMEM (Q_BYTES + 3 * CHUNK_BYTES) // 178176
#define ONES1 0x3C003C00u                 // half2(1.0, 1.0)

__global__ __launch_bounds__(256, 1) void attn_fused(
    const __half* __restrict__ qT, const __half* __restrict__ kT,
    const __half* __restrict__ vv, bf16* __restrict__ aoT)
{
    extern __shared__ char fsm[];
    uint32_t sq = (uint32_t)__cvta_generic_to_shared(fsm);
    uint32_t sring = sq + Q_BYTES;
    const float a2f = 0.0625f * 1.4426950408889634f;   // alpha * log2(e)
    const __half2 a2h = __float2half2_rn(a2f);

    int t = threadIdx.x, wid = t >> 5, lane = t & 31;
    int lr = lane >> 2, lc = lane & 3;
    size_t z = blockIdx.y;
    int q0 = blockIdx.x * 128;

    const __half* qb = qT + z * CHB;
    const __half* kb = kT + z * CHB;
    const __half* vb = vv + z * CHB;

    int arow_l = (lane & 7) + ((lane >> 3) & 1) * 8;
    int akof_l = (lane >> 4) * 8;
    int brow_l = (lane & 7) + ((lane >> 4) & 1) * 8;
    int bkof_l = ((lane >> 3) & 1) * 8;

    // stage q tile
#pragma unroll
    for (int i = 0; i < 16; i++) {
        int idx = i * 256 + t;
        int row = idx >> 5, g = idx & 31;
        CP16(sq + (uint32_t)(row * QSTR + g * 8) * 2,
             qb + (size_t)(q0 + row) * NCH + g * 8);
    }
    CPCOMMIT();

    float out[32][4];
#pragma unroll
    for (int g = 0; g < 32; g++) {
        out[g][0] = 0.f; out[g][1] = 0.f; out[g][2] = 0.f; out[g][3] = 0.f;
    }
    float lacc[4] = {0.f, 0.f, 0.f, 0.f};
    unsigned Sa2[16][2];
    float m_a0 = -1e30f, m_a1 = -1e30f;

    int s_idx = 0;
#define FSTAGE() do {                                                       \
        int ty_ = s_idx & 3, kti_ = s_idx >> 2;                             \
        uint32_t bs = sring + (uint32_t)(s_idx % 3) * CHUNK_BYTES;          \
        if (ty_ < 2) {                                                      \
            const __half* src = kb + (size_t)(kti_ * 128 + ty_ * 64) * NCH; \
            _Pragma("unroll")                                               \
            for (int i = 0; i < 8; i++) {                                   \
                int idx = i * 256 + t; int row = idx >> 5, g = idx & 31;    \
                CP16(bs + (uint32_t)(row * KSTR + g * 8) * 2,               \
                     src + (size_t)row * NCH + g * 8);                      \
            }                                                               \
        } else {                                                            \
            const __half* src = vb + kti_ * 128 + (ty_ - 2) * 64;           \
            _Pragma("unroll")                                               \
            for (int i = 0; i < 8; i++) {                                   \
                int idx = i * 256 + t; int row = idx >> 3, g = idx & 7;     \
                CP16(bs + (uint32_t)(row * VSTR + g * 8) * 2,               \
                     src + (size_t)row * NTOK + g * 8);                     \
            }                                                               \
        }                                                                   \
        CPCOMMIT();                                                         \
        s_idx++;                                                            \
    } while (0)

    FSTAGE();
    FSTAGE();

    int c_idx = 0;
    uint32_t bs_cur;
#define ADV() do {                                                          \
        if (c_idx < 127) CPWAIT1(); else CPWAIT0();                         \
        __syncthreads();                                                    \
        if (s_idx < 128) FSTAGE();                                          \
        bs_cur = sring + (uint32_t)(c_idx % 3) * CHUNK_BYTES;               \
        c_idx++;                                                            \
    } while (0)

    for (int kti = 0; kti < 32; kti++) {
        // ---- S = q . kT^T (fp16 accumulate) : two 64-token halves ----
#pragma unroll
        for (int h = 0; h < 2; h++) {
            ADV();
            if (h == 0) {
#pragma unroll
                for (int j = 0; j < 16; j++) { Sa2[j][0] = 0u; Sa2[j][1] = 0u; }
            }
#pragma unroll
            for (int ks = 0; ks < 16; ks++) {
                unsigned a0, a1, a2, a3;
                LDSM4(a0, a1, a2, a3,
                      sq + (uint32_t)((wid * 16 + arow_l) * QSTR
                                      + ks * 16 + akof_l) * 2);
#pragma unroll
                for (int ng = 0; ng < 4; ng++) {
                    unsigned b0, b1, b2, b3;
                    LDSM4(b0, b1, b2, b3,
                          bs_cur + (uint32_t)((ng * 16 + brow_l) * KSTR
                                              + ks * 16 + bkof_l) * 2);
                    int j = h * 8 + 2 * ng;
                    mma16816hh(Sa2[j],     a0, a1, a2, a3, b0, b1);
                    mma16816hh(Sa2[j + 1], a0, a1, a2, a3, b2, b3);
                }
            }
        }

        // ---- online softmax (exp2 domain, half2) ----
        {
            __half2 x0 = *(__half2*)&Sa2[0][0];
            __half2 x1 = *(__half2*)&Sa2[0][1];
#pragma unroll
            for (int j = 1; j < 16; j++) {
                x0 = __hmax2(x0, *(__half2*)&Sa2[j][0]);
                x1 = __hmax2(x1, *(__half2*)&Sa2[j][1]);
            }
            unsigned u0 = *(unsigned*)&x0, u1 = *(unsigned*)&x1;
            u0 = __shfl_xor_sync(0xffffffffu, u0, 1);
            x0 = __hmax2(x0, *(__half2*)&u0);
            u1 = __shfl_xor_sync(0xffffffffu, u1, 1);
            x1 = __hmax2(x1, *(__half2*)&u1);
            u0 = *(unsigned*)&x0; u1 = *(unsigned*)&x1;
            u0 = __shfl_xor_sync(0xffffffffu, u0, 2);
            x0 = __hmax2(x0, *(__half2*)&u0);
            u1 = __shfl_xor_sync(0xffffffffu, u1, 2);
            x1 = __hmax2(x1, *(__half2*)&u1);
            float t0 = a2f * __half2float(__hmax(__low2half(x0), __high2half(x0)));
            float t1 = a2f * __half2float(__hmax(__low2half(x1), __high2half(x1)));
            float mn0 = fmaxf(m_a0, t0);
            float mn1 = fmaxf(m_a1, t1);

            bool need = (mn0 > m_a0) || (mn1 > m_a1);
            if (__any_sync(0xffffffffu, need)) {
                float sc0 = exp2f(m_a0 - mn0);
                float sc1 = exp2f(m_a1 - mn1);
#pragma unroll
                for (int g = 0; g < 32; g++) {
                    out[g][0] *= sc0; out[g][1] *= sc0;
                    out[g][2] *= sc1; out[g][3] *= sc1;
                }
                lacc[0] *= sc0; lacc[1] *= sc0;
                lacc[2] *= sc1; lacc[3] *= sc1;
                m_a0 = mn0; m_a1 = mn1;
            }

            __half2 nm0 = __float2half2_rn(-m_a0);
            __half2 nm1 = __float2half2_rn(-m_a1);
#pragma unroll
            for (int j = 0; j < 16; j++) {
                __half2 p0 = h2exp2(__hfma2(a2h, *(__half2*)&Sa2[j][0], nm0));
                __half2 p1 = h2exp2(__hfma2(a2h, *(__half2*)&Sa2[j][1], nm1));
                Sa2[j][0] = *(unsigned*)&p0;
                Sa2[j][1] = *(unsigned*)&p1;
            }
        }

        // ---- out += P . v^T (fp32 accumulate); l via ones-column ----
#pragma unroll
        for (int h = 0; h < 2; h++) {
            ADV();
#pragma unroll
            for (int ks = 0; ks < 4; ks++) {
                int j0 = (h * 4 + ks) * 2;
                unsigned a0 = Sa2[j0][0];
                unsigned a1 = Sa2[j0][1];
                unsigned a2 = Sa2[j0 + 1][0];
                unsigned a3 = Sa2[j0 + 1][1];
                mma16816h(lacc, a0, a1, a2, a3, ONES1, ONES1);
#pragma unroll
                for (int ng = 0; ng < 16; ng++) {
                    unsigned b0, b1, b2, b3;
                    LDSM4(b0, b1, b2, b3,
                          bs_cur + (uint32_t)((ng * 16 + brow_l) * VSTR
                                              + ks * 16 + bkof_l) * 2);
                    mma16816h(out[2 * ng],     a0, a1, a2, a3, b0, b1);
                    mma16816h(out[2 * ng + 1], a0, a1, a2, a3, b2, b3);
                }
            }
        }
    }
#undef ADV
#undef FSTAGE

    // ---- epilogue: normalize by l (exact row sums from ones-MMA) ----
    float i0 = 1.f / lacc[0];
    float i1 = 1.f / lacc[2];

    bf16* ao = aoT + z * CHB;
    int r0 = q0 + wid * 16 + lr;
#pragma unroll
    for (int g = 0; g < 32; g++) {
        int col = g * 8 + 2 * lc;
        *(uint32_t*)&ao[(size_t)r0 * NCH + col]       = pkbf(out[g][0] * i0, out[g][1] * i0);
        *(uint32_t*)&ao[(size_t)(r0 + 8) * NCH + col] = pkbf(out[g][2] * i1, out[g][3] * i1);
    }
}

// ---------------------------------------------------------------------------
// kernel_launch — scratch via cudaGetSymbolAddress (true device addresses).
// ---------------------------------------------------------------------------
extern "C" void kernel_launch(void* const* d_in, const int* in_sizes, int n_in,
                              void* d_out, int out_size)
{
    const float* x   = (const float*)d_in[0];
    const float* gns = (const float*)d_in[1];
    const float* gnb = (const float*)d_in[2];
    const float* wq  = (const float*)d_in[3];
    const float* bq  = (const float*)d_in[4];
    const float* wk  = (const float*)d_in[5];
    const float* bk  = (const float*)d_in[6];
    const float* wv  = (const float*)d_in[7];
    const float* bv  = (const float*)d_in[8];
    const float* wo  = (const float*)d_in[9];
    const float* bo  = (const float*)d_in[10];
    float* out = (float*)d_out;

    void *p_hn, *p_hnT, *p_qT, *p_kT, *p_v, *p_aoT, *p_wb;
    cudaGetSymbolAddress(&p_hn,  g_hn);
    cudaGetSymbolAddress(&p_hnT, g_hnT);
    cudaGetSymbolAddress(&p_qT,  g_qT);
    cudaGetSymbolAddress(&p_kT,  g_kT);
    cudaGetSymbolAddress(&p_v,   g_v);
    cudaGetSymbolAddress(&p_aoT, g_aoT);
    cudaGetSymbolAddress(&p_wb,  g_wb);
    float*  hn  = (float*)p_hn;
    bf16*   hnT = (bf16*)p_hnT;
    __half* qT  = (__half*)p_qT;
    __half* kT  = (__half*)p_kT;
    __half* v   = (__half*)p_v;
    bf16*   aoT = (bf16*)p_aoT;
    bf16*   wb  = (bf16*)p_wb;

    cudaFuncSetAttribute(hgemm<2, 2, 0>, cudaFuncAttributeMaxDynamicSharedMemorySize, SMEM_DYN);
    cudaFuncSetAttribute(hgemm<2, 1, 0>, cudaFuncAttributeMaxDynamicSharedMemorySize, SMEM_DYN);
    cudaFuncSetAttribute(hgemm<0, 1, 1>, cudaFuncAttributeMaxDynamicSharedMemorySize, SMEM_DYN);
    cudaFuncSetAttribute(attn_fused, cudaFuncAttributeMaxDynamicSharedMemorySize, FSMEM);

    // 0) bf16 weights + GroupNorm + hnT
    prep_kernel<<<256, 256>>>(wq, wk, wv, wo, wb);
    groupnorm_kernel<<<NB * 32, 256>>>(x, gns, gnb, hn);
    transpose_bf16_kernel<<<dim3(NTOK / 32, NCH / 32, NB), 256>>>(hn, hnT);

    // 1) qT[tok][ch] = hnT . wq^T + bq (fp16 out); kT likewise
    hgemm<2, 2, 0><<<dim3(2, 32, NB), 256, SMEM_DYN>>>(
        hnT, wb, qT, bq, nullptr, 1.f, 1.f,
        NTOK, NCH, NCH, CHB, 0, CHB);
    hgemm<2, 2, 0><<<dim3(2, 32, NB), 256, SMEM_DYN>>>(
        hnT, wb + 65536, kT, bk, nullptr, 1.f, 1.f,
        NTOK, NCH, NCH, CHB, 0, CHB);
    // v[ch][tok] = wv . hnT^T + bv (fp16 out)
    hgemm<2, 1, 0><<<dim3(32, 2, NB), 256, SMEM_DYN>>>(
        wb + 131072, hnT, v, bv, nullptr, 1.f, 1.f,
        NCH, NTOK, NCH, 0, CHB, CHB);

    // 2) fused attention (fp16 S-path)
    attn_fused<<<dim3(32, NB), 256, FSMEM>>>(qT, kT, v, aoT);

    // 3) out[ch][tok] = (wo . aoT^T + bo + x) / sqrt(2)
    hgemm<0, 1, 1><<<dim3(32, 2, NB), 256, SMEM_DYN>>>(
        wb + 196608, aoT, out, bo, x, 1.f, 0.70710678118654752f,
        NCH, NTOK, NCH, 0, CHB, CHB);
}